// round 15
// baseline (speedup 1.0000x reference)
#include <cuda_runtime.h>
#include <cuda_fp16.h>
#include <stdint.h>

// Problem constants
#define Lq     512
#define BATCH  4
#define SCALEF 0.125f
#define LOG2E  1.4426950408889634f

// ---------------- scratch ----------------
__device__ __half g_memh[(size_t)6144 * 512];
__device__ __half g_xh  [(size_t)2048 * 512];
__device__ __half g_posh[(size_t)8192 * 512];
__device__ __half g_wkvh[(size_t)512 * 1024];
__device__ __half g_wrelh[(size_t)512 * 512];
__device__ __half g_wqh [(size_t)512 * 512];
__device__ __half g_woh [(size_t)512 * 512];
__device__ __half g_kv  [(size_t)8192 * 1024];
__device__ __half g_rel [(size_t)8192 * 512];
__device__ __half g_qh  [(size_t)2048 * 512];
__device__ __half g_prob[(size_t)32 * 512 * 2048];      // i-major: [i][bn][j]
__device__ float  g_rsum[(size_t)32 * 512];
__device__ __half g_vec [(size_t)2048 * 512];
__device__ float  g_y   [(size_t)2048 * 512];

// ---------------- helpers ----------------
__device__ __forceinline__ void mma_f16(float* d, const uint32_t* a,
                                        const uint32_t* b, const float* c) {
    asm volatile(
        "mma.sync.aligned.m16n8k16.row.col.f32.f16.f16.f32 "
        "{%0,%1,%2,%3}, {%4,%5,%6,%7}, {%8,%9}, {%10,%11,%12,%13};"
        : "=f"(d[0]), "=f"(d[1]), "=f"(d[2]), "=f"(d[3])
        : "r"(a[0]), "r"(a[1]), "r"(a[2]), "r"(a[3]),
          "r"(b[0]), "r"(b[1]),
          "f"(c[0]), "f"(c[1]), "f"(c[2]), "f"(c[3]));
}

__device__ __forceinline__ void ldsm_x4_t(uint32_t& r0, uint32_t& r1,
                                          uint32_t& r2, uint32_t& r3, uint32_t addr) {
    asm volatile("ldmatrix.sync.aligned.m8n8.x4.trans.shared.b16 {%0,%1,%2,%3}, [%4];"
                 : "=r"(r0), "=r"(r1), "=r"(r2), "=r"(r3) : "r"(addr));
}
__device__ __forceinline__ void ldsm_x4(uint32_t& r0, uint32_t& r1,
                                        uint32_t& r2, uint32_t& r3, uint32_t addr) {
    asm volatile("ldmatrix.sync.aligned.m8n8.x4.shared.b16 {%0,%1,%2,%3}, [%4];"
                 : "=r"(r0), "=r"(r1), "=r"(r2), "=r"(r3) : "r"(addr));
}

__device__ __forceinline__ void cp16(void* dst, const void* src) {
    uint32_t d = (uint32_t)__cvta_generic_to_shared(dst);
    asm volatile("cp.async.cg.shared.global [%0], [%1], 16;" :: "r"(d), "l"(src));
}
#define CP_COMMIT() asm volatile("cp.async.commit_group;")
#define CP_WAIT1()  asm volatile("cp.async.wait_group 1;")
#define CP_WAIT2()  asm volatile("cp.async.wait_group 2;")

__device__ __forceinline__ float ex2f(float x) {
    float r;
    asm("ex2.approx.f32 %0, %1;" : "=f"(r) : "f"(x));
    return r;
}

__device__ __forceinline__ float warpRedSum(float v) {
#pragma unroll
    for (int o = 16; o > 0; o >>= 1) v += __shfl_xor_sync(0xffffffffu, v, o);
    return v;
}
__device__ __forceinline__ float blockRedSum(float v, float* red) {
    v = warpRedSum(v);
    int w = threadIdx.x >> 5, l = threadIdx.x & 31;
    if (!l) red[w] = v;
    __syncthreads();
    if (threadIdx.x < 32) {
        float x = (l < 8) ? red[l] : 0.f;
        x = warpRedSum(x);
        if (!l) red[0] = x;
    }
    __syncthreads();
    float r = red[0];
    __syncthreads();
    return r;
}

// ============================================================================
// Fused float->half conversion (7 arrays)
// ============================================================================
struct ConvJob {
    const float* src[7];
    __half* dst[7];
    int n4[7];
};

__global__ void conv_f2h(ConvJob j, int total4) {
    int idx = blockIdx.x * blockDim.x + threadIdx.x;
    if (idx >= total4) return;
    int off = idx, seg = 0;
#pragma unroll
    for (int s = 0; s < 6; s++)
        if (off >= j.n4[seg]) { off -= j.n4[seg]; seg++; }
    float4 v = ((const float4*)j.src[seg])[off];
    __half2* d = (__half2*)j.dst[seg] + off * 2;
    d[0] = __floats2half2_rn(v.x, v.y);
    d[1] = __floats2half2_rn(v.z, v.w);
}

// ============================================================================
// fp16 projection kernel (4 GEMMs, one launch). 3-stage cp.async, ldsm A+B.
// ============================================================================
struct DescH {
    const __half* A; const __half* B; void* C;
    int N, K, nblk, blk0, h;
};

#define PA_ST 40
#define PB_ST 136
__global__ __launch_bounds__(256) void proj_h(DescH d0, DescH d1, DescH d2, DescH d3) {
    extern __shared__ char smraw[];
    __half* As = (__half*)smraw;
    __half* Bs = As + 3 * 128 * PA_ST;

    DescH d = d3;
    int bid = blockIdx.x;
    if (bid < d1.blk0) d = d0;
    else if (bid < d2.blk0) d = d1;
    else if (bid < d3.blk0) d = d2;
    int local = bid - d.blk0;
    int m0 = (local / d.nblk) * 128, n0 = (local % d.nblk) * 128;
    const int N = d.N, K = d.K;

    int tid = threadIdx.x;
    int warp = tid >> 5, lane = tid & 31;
    int g = lane >> 2, c = lane & 3;
    int wm = (warp >> 2) * 64;
    int wn = (warp & 3) * 32;
    int mat = lane >> 3;
    int lrow = (mat & 1) * 8 + (lane & 7);
    int lcol = (mat >> 1) * 8;
    // A fragment ldsm lane term: row = (mat&1)*8 + l8, col = (mat>>1)*8
    uint32_t a_lane_term =
        (uint32_t)((((mat & 1) * 8 + (lane & 7)) * PA_ST + (mat >> 1) * 8) * 2);

    float acc[4][4][4];
#pragma unroll
    for (int mt = 0; mt < 4; mt++)
#pragma unroll
        for (int nt = 0; nt < 4; nt++)
#pragma unroll
            for (int e = 0; e < 4; e++) acc[mt][nt][e] = 0.f;

    int nk = K >> 5;
    auto loadStage = [&](int st, int k0) {
#pragma unroll
        for (int w = 0; w < 2; w++) {
            int idx = tid + w * 256;
            int r = idx >> 2, ch = (idx & 3) * 8;
            cp16(As + st * 128 * PA_ST + r * PA_ST + ch,
                 d.A + (size_t)(m0 + r) * K + k0 + ch);
        }
#pragma unroll
        for (int w = 0; w < 2; w++) {
            int idx = tid + w * 256;
            int r = idx >> 4, ch = (idx & 15) * 8;
            cp16(Bs + st * 32 * PB_ST + r * PB_ST + ch,
                 d.B + (size_t)(k0 + r) * N + n0 + ch);
        }
    };

    loadStage(0, 0);
    CP_COMMIT();
    loadStage(1, 32);
    CP_COMMIT();

    int st = 0;
    for (int kt = 0; kt < nk; kt++) {
        if (kt + 2 < nk) loadStage((st + 2) % 3, (kt + 2) * 32);
        CP_COMMIT();
        CP_WAIT2();
        __syncthreads();

        uint32_t abase = (uint32_t)__cvta_generic_to_shared(As + st * 128 * PA_ST)
                         + a_lane_term;
        uint32_t bbase = (uint32_t)__cvta_generic_to_shared(Bs + st * 32 * PB_ST);
#pragma unroll
        for (int ks = 0; ks < 2; ks++) {
            int k = ks * 16;
            uint32_t af[4][4], bf[4][2];
#pragma unroll
            for (int mt = 0; mt < 4; mt++) {
                uint32_t addr = abase +
                    (uint32_t)(((wm + mt * 16) * PA_ST + k) * 2);
                ldsm_x4(af[mt][0], af[mt][1], af[mt][2], af[mt][3], addr);
            }
#pragma unroll
            for (int p = 0; p < 2; p++) {
                uint32_t addr = bbase +
                    (uint32_t)(((k + lrow) * PB_ST + wn + p * 16 + lcol) * 2);
                uint32_t r0, r1, r2, r3;
                ldsm_x4_t(r0, r1, r2, r3, addr);
                bf[2 * p][0] = r0; bf[2 * p][1] = r1;
                bf[2 * p + 1][0] = r2; bf[2 * p + 1][1] = r3;
            }
#pragma unroll
            for (int mt = 0; mt < 4; mt++)
#pragma unroll
                for (int nt = 0; nt < 4; nt++)
                    mma_f16(acc[mt][nt], af[mt], bf[nt], acc[mt][nt]);
        }
        __syncthreads();
        st = (st + 1) % 3;
    }

#pragma unroll
    for (int mt = 0; mt < 4; mt++)
#pragma unroll
        for (int nt = 0; nt < 4; nt++) {
            int row = m0 + wm + mt * 16 + g;
            int col = n0 + wn + nt * 8 + c * 2;
            if (d.h) {
                __half* Ch = (__half*)d.C;
                *(__half2*)(Ch + (size_t)row * N + col) =
                    __floats2half2_rn(acc[mt][nt][0], acc[mt][nt][1]);
                *(__half2*)(Ch + (size_t)(row + 8) * N + col) =
                    __floats2half2_rn(acc[mt][nt][2], acc[mt][nt][3]);
            } else {
                float* Cf = (float*)d.C;
                *(float2*)(Cf + (size_t)row * N + col) =
                    make_float2(acc[mt][nt][0], acc[mt][nt][1]);
                *(float2*)(Cf + (size_t)(row + 8) * N + col) =
                    make_float2(acc[mt][nt][2], acc[mt][nt][3]);
            }
        }
}

// ============================================================================
// fp16 GEMM BN=64 with fp32 residual add (W_o)
// ============================================================================
#define GB_ST 72
__global__ __launch_bounds__(256) void gemm64_h(
        const __half* __restrict__ A, const __half* __restrict__ B,
        const float* __restrict__ Cadd, float* __restrict__ C,
        int M, int N, int K) {
    extern __shared__ char smraw[];
    __half* As = (__half*)smraw;
    __half* Bs = As + 2 * 128 * PA_ST;

    int m0 = blockIdx.y * 128, n0 = blockIdx.x * 64;
    int tid = threadIdx.x;
    int warp = tid >> 5, lane = tid & 31;
    int g = lane >> 2, c = lane & 3;
    int wm = (warp >> 2) * 64;
    int wn = (warp & 3) * 16;
    int mat = lane >> 3;
    int lrow = (mat & 1) * 8 + (lane & 7);
    int lcol = (mat >> 1) * 8;
    uint32_t a_lane_term =
        (uint32_t)((((mat & 1) * 8 + (lane & 7)) * PA_ST + (mat >> 1) * 8) * 2);

    float acc[4][2][4];
#pragma unroll
    for (int mt = 0; mt < 4; mt++)
#pragma unroll
        for (int nt = 0; nt < 2; nt++)
#pragma unroll
            for (int e = 0; e < 4; e++) acc[mt][nt][e] = 0.f;

    int nk = K >> 5;
    auto loadStage = [&](int st, int k0) {
#pragma unroll
        for (int w = 0; w < 2; w++) {
            int idx = tid + w * 256;
            int r = idx >> 2, ch = (idx & 3) * 8;
            cp16(As + st * 128 * PA_ST + r * PA_ST + ch,
                 A + (size_t)(m0 + r) * K + k0 + ch);
        }
        {
            int r = tid >> 3, ch = (tid & 7) * 8;
            if (r < 32)
                cp16(Bs + st * 32 * GB_ST + r * GB_ST + ch,
                     B + (size_t)(k0 + r) * N + n0 + ch);
        }
    };

    loadStage(0, 0);
    CP_COMMIT();

    for (int kt = 0; kt < nk; kt++) {
        int cur = kt & 1;
        if (kt + 1 < nk) loadStage((kt + 1) & 1, (kt + 1) * 32);
        CP_COMMIT();
        CP_WAIT1();
        __syncthreads();

        uint32_t abase = (uint32_t)__cvta_generic_to_shared(As + cur * 128 * PA_ST)
                         + a_lane_term;
        uint32_t bbase = (uint32_t)__cvta_generic_to_shared(Bs + cur * 32 * GB_ST);
#pragma unroll
        for (int ks = 0; ks < 2; ks++) {
            int k = ks * 16;
            uint32_t af[4][4], bf[2][2];
#pragma unroll
            for (int mt = 0; mt < 4; mt++) {
                uint32_t addr = abase +
                    (uint32_t)(((wm + mt * 16) * PA_ST + k) * 2);
                ldsm_x4(af[mt][0], af[mt][1], af[mt][2], af[mt][3], addr);
            }
            {
                uint32_t addr = bbase +
                    (uint32_t)(((k + lrow) * GB_ST + wn + lcol) * 2);
                uint32_t r0, r1, r2, r3;
                ldsm_x4_t(r0, r1, r2, r3, addr);
                bf[0][0] = r0; bf[0][1] = r1;
                bf[1][0] = r2; bf[1][1] = r3;
            }
#pragma unroll
            for (int mt = 0; mt < 4; mt++)
#pragma unroll
                for (int nt = 0; nt < 2; nt++)
                    mma_f16(acc[mt][nt], af[mt], bf[nt], acc[mt][nt]);
        }
        __syncthreads();
    }

#pragma unroll
    for (int mt = 0; mt < 4; mt++)
#pragma unroll
        for (int nt = 0; nt < 2; nt++) {
            int row = m0 + wm + mt * 16 + g;
            int col = n0 + wn + nt * 8 + c * 2;
            const float* a0 = Cadd + (size_t)row * N + col;
            const float* a1 = Cadd + (size_t)(row + 8) * N + col;
            *(float2*)(C + (size_t)row * N + col) =
                make_float2(acc[mt][nt][0] + a0[0], acc[mt][nt][1] + a0[1]);
            *(float2*)(C + (size_t)(row + 8) * N + col) =
                make_float2(acc[mt][nt][2] + a1[0], acc[mt][nt][3] + a1[1]);
        }
}

// ============================================================================
// FLASH-FUSED score + exp + PV kernel, 512 threads (16 warps: 4 m x 4 j).
// No P zero-fill for skipped tiles (attn masks analytically).
// ============================================================================
__global__ __launch_bounds__(512, 1) void score_pv(
        const __half* __restrict__ Q, const float* __restrict__ pbu,
        const float* __restrict__ pbv, const __half* __restrict__ KV,
        const __half* __restrict__ REL, const float* __restrict__ ib,
        __half* __restrict__ P, float* __restrict__ rsum,
        __half* __restrict__ vec) {
    extern __shared__ char smraw[];
    __half* qu_s  = (__half*)smraw;               // [64][72]
    __half* qv_s  = qu_s + 64 * 72;               // [64][72]
    __half* k_s   = qv_s + 64 * 72;               // [2][128*72]
    __half* v_s   = k_s + 2 * 128 * 72;           // [2][128*72]
    __half* rel_s = v_s + 2 * 128 * 72;           // [2][128*72]
    float*  bd_s  = (float*)(rel_s + 2 * 128 * 72);  // [2][64*132]; vb aliases
    float*  rows  = bd_s + 2 * 64 * 132;          // [64]
    float*  gate_s = rows + 64;                   // [64][4]

    int bn = blockIdx.y;
    int b = bn >> 3, n = bn & 7;
    int i0 = blockIdx.x * 64;
    int tid = threadIdx.x;
    int m_base = 448 - i0;

    if (tid < 64) rows[tid] = 0.f;
    if (tid < 256)
        gate_s[tid] = ib[((size_t)(i0 + (tid >> 2)) * 4 + b) * 4 + (tid & 3)];

    const float QS = SCALEF * LOG2E;
#pragma unroll
    for (int w = 0; w < 2; w++) {
        int idx = tid + w * 512;
        int r = idx >> 4, c4 = (idx & 15) * 4;
        const __half2* qsrc =
            (const __half2*)(Q + (size_t)(i0 + r) * 2048 + b * 512 + n * 64 + c4);
        float2 q0 = __half22float2(qsrc[0]);
        float2 q1 = __half22float2(qsrc[1]);
        float4 bu = *(const float4*)(pbu + n * 64 + c4);
        float4 bv = *(const float4*)(pbv + n * 64 + c4);
        *(__half2*)(qu_s + r * 72 + c4) =
            __floats2half2_rn((q0.x + bu.x) * QS, (q0.y + bu.y) * QS);
        *(__half2*)(qu_s + r * 72 + c4 + 2) =
            __floats2half2_rn((q1.x + bu.z) * QS, (q1.y + bu.w) * QS);
        *(__half2*)(qv_s + r * 72 + c4) =
            __floats2half2_rn((q0.x + bv.x) * QS, (q0.y + bv.y) * QS);
        *(__half2*)(qv_s + r * 72 + c4 + 2) =
            __floats2half2_rn((q1.x + bv.z) * QS, (q1.y + bv.w) * QS);
    }

    const __half* Kb = KV + b * 1024 + n * 64;
    const __half* Vb = KV + b * 1024 + 512 + n * 64;
    const __half* Rb = REL + b * 512 + n * 64;

    auto loadK = [&](int st, int j0) {
#pragma unroll
        for (int w = 0; w < 2; w++) {
            int idx = tid + w * 512;
            int r = idx >> 3, ch = (idx & 7) * 8;
            cp16(k_s + st * 128 * 72 + r * 72 + ch,
                 Kb + (size_t)(j0 + r) * 4096 + ch);
        }
    };
    auto loadV = [&](int st, int j0) {
#pragma unroll
        for (int w = 0; w < 2; w++) {
            int idx = tid + w * 512;
            int r = idx >> 3, ch = (idx & 7) * 8;
            cp16(v_s + st * 128 * 72 + r * 72 + ch,
                 Vb + (size_t)(j0 + r) * 4096 + ch);
        }
    };
    auto loadR = [&](int chunk) {
        int st = chunk & 1;
        int mc = m_base + chunk * 128;
#pragma unroll
        for (int w = 0; w < 2; w++) {
            int idx = tid + w * 512;
            int r = idx >> 3, ch = (idx & 7) * 8;
            int mr = mc + r; if (mr > 2047) mr = 2047;
            cp16(rel_s + st * 128 * 72 + r * 72 + ch,
                 Rb + (size_t)mr * 2048 + ch);
        }
    };

    int ntiles = ((1599 + i0) >> 7) + 1;
    if (ntiles > 16) ntiles = 16;

    int warp = tid >> 5, lane = tid & 31;
    int g = lane >> 2, c = lane & 3;
    int wm  = (warp >> 2) * 16;
    int wj  = warp & 3;
    int wnA = wj * 32;

    int mat = lane >> 3;
    int lrow = (mat & 1) * 8 + (lane & 7);
    int lcol = (mat >> 1) * 8;
    int ntq = mat >> 1;
    int dq  = mat & 1;
    int l8  = lane & 7;
    uint32_t frag_row_term =
        (uint32_t)(((wnA + ntq * 8 + l8) * 72 + dq * 8) * 2);

    // prologue loads
    loadR(0);
    CP_COMMIT();
    loadK(0, 0); loadV(0, 0); loadR(1);
    CP_COMMIT();
    CP_WAIT1();
    __syncthreads();

    // hoist q fragments
    uint32_t au_r[4][4], av_r[4][4];
#pragma unroll
    for (int kk = 0; kk < 4; kk++) {
        int k = kk * 16;
        const __half* bu = qu_s + (wm + g) * 72 + k + 2 * c;
        const __half* bv = qv_s + (wm + g) * 72 + k + 2 * c;
        au_r[kk][0] = *(const uint32_t*)(bu);
        au_r[kk][1] = *(const uint32_t*)(bu + 8 * 72);
        au_r[kk][2] = *(const uint32_t*)(bu + 8);
        au_r[kk][3] = *(const uint32_t*)(bu + 8 * 72 + 8);
        av_r[kk][0] = *(const uint32_t*)(bv);
        av_r[kk][1] = *(const uint32_t*)(bv + 8 * 72);
        av_r[kk][2] = *(const uint32_t*)(bv + 8);
        av_r[kk][3] = *(const uint32_t*)(bv + 8 * 72 + 8);
    }

    // BD chunk 0 -> bd_s[0]
    {
        uint32_t rbase = (uint32_t)__cvta_generic_to_shared(rel_s) + frag_row_term;
        float accb[4][4];
#pragma unroll
        for (int nt = 0; nt < 4; nt++)
#pragma unroll
            for (int e = 0; e < 4; e++) accb[nt][e] = 0.f;
#pragma unroll
        for (int kk = 0; kk < 4; kk++) {
            uint32_t br[4][2];
            ldsm_x4(br[0][0], br[0][1], br[1][0], br[1][1], rbase + kk * 32);
            ldsm_x4(br[2][0], br[2][1], br[3][0], br[3][1], rbase + 2304 + kk * 32);
#pragma unroll
            for (int nt = 0; nt < 4; nt++)
                mma_f16(accb[nt], av_r[kk], br[nt], accb[nt]);
        }
#pragma unroll
        for (int nt = 0; nt < 4; nt++) {
            int row = wm + g;
            int col = wnA + nt * 8 + c * 2;
            *(float2*)(bd_s + row * 132 + col) = make_float2(accb[nt][0], accb[nt][1]);
            *(float2*)(bd_s + (row + 8) * 132 + col) = make_float2(accb[nt][2], accb[nt][3]);
        }
    }

    float rs[2] = {0.f, 0.f};
    float pvacc[8][4];
#pragma unroll
    for (int nd = 0; nd < 8; nd++)
#pragma unroll
        for (int e = 0; e < 4; e++) pvacc[nd][e] = 0.f;

    __half* Pb = P + ((size_t)i0 * 32 + bn) * 2048;

    for (int jt = 0; jt < ntiles; jt++) {
        int cur = jt & 1;
        if (jt + 1 < ntiles) {
            loadK((jt + 1) & 1, (jt + 1) * 128);
            loadV((jt + 1) & 1, (jt + 1) * 128);
        }
        if (jt + 2 <= ntiles) loadR(jt + 2);
        CP_COMMIT();
        CP_WAIT1();
        __syncthreads();

        uint32_t kfb = (uint32_t)__cvta_generic_to_shared(k_s + cur * 128 * 72) + frag_row_term;
        uint32_t rfb = (uint32_t)__cvta_generic_to_shared(rel_s + ((jt + 1) & 1) * 128 * 72) + frag_row_term;

        float acca[4][4], accb[4][4];
#pragma unroll
        for (int nt = 0; nt < 4; nt++)
#pragma unroll
            for (int e = 0; e < 4; e++) { acca[nt][e] = 0.f; accb[nt][e] = 0.f; }

#pragma unroll
        for (int kk = 0; kk < 4; kk++) {
            uint32_t bk[4][2], br[4][2];
            ldsm_x4(bk[0][0], bk[0][1], bk[1][0], bk[1][1], kfb + kk * 32);
            ldsm_x4(bk[2][0], bk[2][1], bk[3][0], bk[3][1], kfb + 2304 + kk * 32);
            ldsm_x4(br[0][0], br[0][1], br[1][0], br[1][1], rfb + kk * 32);
            ldsm_x4(br[2][0], br[2][1], br[3][0], br[3][1], rfb + 2304 + kk * 32);
#pragma unroll
            for (int nt = 0; nt < 4; nt++) {
                mma_f16(acca[nt], au_r[kk], bk[nt], acca[nt]);
                mma_f16(accb[nt], av_r[kk], br[nt], accb[nt]);
            }
        }

        // store BD chunk jt+1
        float* bdo = bd_s + ((jt + 1) & 1) * 64 * 132;
#pragma unroll
        for (int nt = 0; nt < 4; nt++) {
            int row = wm + g;
            int col = wnA + nt * 8 + c * 2;
            *(float2*)(bdo + row * 132 + col) = make_float2(accb[nt][0], accb[nt][1]);
            *(float2*)(bdo + (row + 8) * 132 + col) = make_float2(accb[nt][2], accb[nt][3]);
        }
        __syncthreads();

        // epilogue
        int j0 = jt * 128;
        int segA = j0 >> 9;
        bool last = (jt == ntiles - 1);
        const float* bd_lo = bd_s + (jt & 1) * 64 * 132;
        const float* bd_hi = bd_s + ((jt + 1) & 1) * 64 * 132;
        uint32_t pe2[4][2];
#pragma unroll
        for (int half = 0; half < 2; half++) {
            int i_loc = wm + g + half * 8;
            int i = i0 + i_loc;
            int mrow = j0 + 511 - i;
            float gA = gate_s[i_loc * 4 + segA];
            const float* gt = gate_s + i_loc * 4;
            int mlo = mrow + wnA;
            int slo = mlo >> 9; if (slo > 3) slo = 3;
            int shi = (mlo + 31) >> 9; if (shi > 3) shi = 3;
            float glo = gt[slo], ghi = gt[shi];
            int jcross = (((mlo >> 9) + 1) << 9) - mrow;
            int ocross = 65 + i_loc;
            const float* bdrow_lo = bd_lo + i_loc * 132 + 63 - i_loc;
            const float* bdrow_hi = bd_hi + i_loc * 132 + 63 - i_loc - 128;
            int jmax_loc = 1536 + i - j0;
#pragma unroll
            for (int nt = 0; nt < 4; nt++) {
                float a0 = acca[nt][half * 2];
                float a1 = acca[nt][half * 2 + 1];
                float pe[2];
#pragma unroll
                for (int e = 0; e < 2; e++) {
                    int j_loc = wnA + nt * 8 + c * 2 + e;
                    float gB = (j_loc >= jcross) ? ghi : glo;
                    const float* bp = (j_loc < ocross) ? bdrow_lo : bdrow_hi;
                    float bd = bp[j_loc];
                    float ac = e ? a1 : a0;
                    float s = fmaf(gA, ac, gB * bd);
                    pe[e] = ex2f(s);
                }
                if (last) {
                    int j_loc0 = wnA + nt * 8 + c * 2;
                    if (j_loc0 > jmax_loc) pe[0] = 0.f;
                    if (j_loc0 + 1 > jmax_loc) pe[1] = 0.f;
                }
                rs[half] += pe[0] + pe[1];
                __half2 h2 = __floats2half2_rn(pe[0], pe[1]);
                pe2[nt][half] = *(uint32_t*)&h2;
                *(__half2*)(Pb + (size_t)i_loc * 65536 + j0 + wnA + nt * 8 + c * 2) = h2;
            }
        }

        // PV MMA
        {
            uint32_t vbase = (uint32_t)__cvta_generic_to_shared(v_s + cur * 128 * 72);
#pragma unroll
            for (int kk2 = 0; kk2 < 2; kk2++) {
                uint32_t bf[8][2];
#pragma unroll
                for (int p = 0; p < 4; p++) {
                    uint32_t addr = vbase +
                        (uint32_t)(((wnA + kk2 * 16 + lrow) * 72 + p * 16 + lcol) * 2);
                    uint32_t r0, r1, r2, r3;
                    ldsm_x4_t(r0, r1, r2, r3, addr);
                    bf[2 * p][0] = r0; bf[2 * p][1] = r1;
                    bf[2 * p + 1][0] = r2; bf[2 * p + 1][1] = r3;
                }
                uint32_t af[4];
                af[0] = pe2[2 * kk2][0];
                af[1] = pe2[2 * kk2][1];
                af[2] = pe2[2 * kk2 + 1][0];
                af[3] = pe2[2 * kk2 + 1][1];
#pragma unroll
                for (int nd = 0; nd < 8; nd++)
                    mma_f16(pvacc[nd], af, bf[nd], pvacc[nd]);
            }
        }
        __syncthreads();
    }

    atomicAdd(&rows[wm + g], rs[0]);
    atomicAdd(&rows[wm + g + 8], rs[1]);
    __syncthreads();
    if (tid < 64) rows[tid] = 1.f / rows[tid];

    float* vb = bd_s;
    for (int idx = tid; idx < 64 * 68; idx += 512) vb[idx] = 0.f;
    __syncthreads();

    for (int r = 0; r < 4; r++) {
        if (wj == r) {
#pragma unroll
            for (int nd = 0; nd < 8; nd++)
#pragma unroll
                for (int e = 0; e < 4; e++) {
                    int row = wm + g + ((e >> 1) ? 8 : 0);
                    int col = nd * 8 + c * 2 + (e & 1);
                    vb[row * 68 + col] += pvacc[nd][e];
                }
        }
        __syncthreads();
    }

#pragma unroll
    for (int t = 0; t < 4; t++) {
        int e = tid + t * 512;
        int row = e >> 5, cp = e & 31;
        float inv = rows[row];
        float v0 = vb[row * 68 + cp * 2] * inv;
        float v1 = vb[row * 68 + cp * 2 + 1] * inv;
        *(__half2*)(vec + ((size_t)(i0 + row) * 4 + b) * 512 + n * 64 + cp * 2) =
            __floats2half2_rn(v0, v1);
    }
    if (tid < 64)
        rsum[(size_t)bn * 512 + i0 + tid] = rows[tid];
}

// ---------------- attn matrix: analytic masking (skip masked loads) --------
__global__ void attn_kernel(const __half* __restrict__ P,
                            const float* __restrict__ rsum,
                            float* __restrict__ attn) {
    __shared__ float invs[32];
    int i = blockIdx.x;
    int tid = threadIdx.x;
    if (tid < 32) invs[tid] = rsum[(size_t)tid * 512 + i];
    __syncthreads();

    int j0t = tid * 8;
    int jmax = 1536 + i;
    float* dst = attn + (size_t)i * 2048 + j0t;
    if (j0t > jmax) {
#pragma unroll
        for (int e = 0; e < 8; e++) dst[e] = 0.f;
        return;
    }

    float acc[8] = {0.f, 0.f, 0.f, 0.f, 0.f, 0.f, 0.f, 0.f};
    const __half* base = P + (size_t)i * 65536 + j0t;
#pragma unroll
    for (int bn = 0; bn < 32; bn += 8) {
        uint4 raw[8];
#pragma unroll
        for (int u = 0; u < 8; u++)
            raw[u] = *(const uint4*)(base + (size_t)(bn + u) * 2048);
#pragma unroll
        for (int u = 0; u < 8; u++) {
            float inv = invs[bn + u];
            const __half2* h = (const __half2*)&raw[u];
#pragma unroll
            for (int e = 0; e < 4; e++) {
                float2 f = __half22float2(h[e]);
                acc[e * 2]     += inv * f.x;
                acc[e * 2 + 1] += inv * f.y;
            }
        }
    }
    int nvalid = jmax - j0t + 1;
    if (nvalid > 8) nvalid = 8;
#pragma unroll
    for (int e = 0; e < 8; e++)
        dst[e] = (e < nvalid) ? acc[e] * (1.f / 32.f) : 0.f;
}

// ---------------- layernorm ----------------
__global__ void ln_kernel(const float* __restrict__ y, const float* __restrict__ g,
                          const float* __restrict__ be, float* __restrict__ out) {
    __shared__ float red[32];
    int r = blockIdx.x;
    int tid = threadIdx.x;
    float v0 = y[(size_t)r * 512 + tid];
    float v1 = y[(size_t)r * 512 + tid + 256];
    float mean = blockRedSum(v0 + v1, red) * (1.f / 512.f);
    float d0 = v0 - mean, d1 = v1 - mean;
    float var = blockRedSum(d0 * d0 + d1 * d1, red) * (1.f / 512.f);
    float rstd = rsqrtf(var + 1e-5f);
    out[(size_t)r * 512 + tid]       = d0 * rstd * g[tid] + be[tid];
    out[(size_t)r * 512 + tid + 256] = d1 * rstd * g[tid + 256] + be[tid + 256];
}

// ---------------- launch ----------------
#define SMEM_PH  ((3 * 128 * PA_ST + 3 * 32 * PB_ST) * 2)
#define SMEM_GH  ((2 * 128 * PA_ST + 2 * 32 * GB_ST) * 2)
#define SMEM_SPV ((64*72*2 + 3*2*128*72) * 2 + (2*64*132 + 64 + 256) * 4)

extern "C" void kernel_launch(void* const* d_in, const int* in_sizes, int n_in,
                              void* d_out, int out_size) {
    (void)in_sizes; (void)n_in; (void)out_size;
    const float* x       = (const float*)d_in[0];
    const float* memory  = (const float*)d_in[1];
    const float* pos_emb = (const float*)d_in[2];
    const float* pbu     = (const float*)d_in[3];
    const float* pbv     = (const float*)d_in[4];
    const float* ib      = (const float*)d_in[6];
    const float* W_q     = (const float*)d_in[7];
    const float* W_kv    = (const float*)d_in[8];
    const float* W_rel   = (const float*)d_in[9];
    const float* W_o     = (const float*)d_in[10];
    const float* ln_g    = (const float*)d_in[11];
    const float* ln_b    = (const float*)d_in[12];

    float* out  = (float*)d_out;
    float* attn = out + (size_t)Lq * BATCH * 512;

    __half *memh, *xh, *posh, *wkvh, *wrelh, *wqh, *woh;
    __half *kvh, *relh, *qh, *prob, *vec;
    float *rs, *y;
    cudaGetSymbolAddress((void**)&memh,  g_memh);
    cudaGetSymbolAddress((void**)&xh,    g_xh);
    cudaGetSymbolAddress((void**)&posh,  g_posh);
    cudaGetSymbolAddress((void**)&wkvh,  g_wkvh);
    cudaGetSymbolAddress((void**)&wrelh, g_wrelh);
    cudaGetSymbolAddress((void**)&wqh,   g_wqh);
    cudaGetSymbolAddress((void**)&woh,   g_woh);
    cudaGetSymbolAddress((void**)&kvh,   g_kv);
    cudaGetSymbolAddress((void**)&relh,  g_rel);
    cudaGetSymbolAddress((void**)&qh,    g_qh);
    cudaGetSymbolAddress((void**)&prob,  g_prob);
    cudaGetSymbolAddress((void**)&rs,    g_rsum);
    cudaGetSymbolAddress((void**)&vec,   g_vec);
    cudaGetSymbolAddress((void**)&y,     g_y);

    static cudaStream_t s2 = nullptr;
    static cudaEvent_t ev1 = nullptr, ev2 = nullptr;
    static bool attr_set = false;
    if (!attr_set) {
        cudaFuncSetAttribute(proj_h,
                             cudaFuncAttributeMaxDynamicSharedMemorySize, SMEM_PH);
        cudaFuncSetAttribute(gemm64_h,
                             cudaFuncAttributeMaxDynamicSharedMemorySize, SMEM_GH);
        cudaFuncSetAttribute(score_pv,
                             cudaFuncAttributeMaxDynamicSharedMemorySize, SMEM_SPV);
        cudaStreamCreateWithFlags(&s2, cudaStreamNonBlocking);
        cudaEventCreateWithFlags(&ev1, cudaEventDisableTiming);
        cudaEventCreateWithFlags(&ev2, cudaEventDisableTiming);
        attr_set = true;
    }

    // 0) convert fp32 inputs -> fp16
    ConvJob cj;
    cj.src[0] = memory;  cj.dst[0] = memh;  cj.n4[0] = 6144 * 512 / 4;
    cj.src[1] = x;       cj.dst[1] = xh;    cj.n4[1] = 2048 * 512 / 4;
    cj.src[2] = pos_emb; cj.dst[2] = posh;  cj.n4[2] = 8192 * 512 / 4;
    cj.src[3] = W_kv;    cj.dst[3] = wkvh;  cj.n4[3] = 512 * 1024 / 4;
    cj.src[4] = W_rel;   cj.dst[4] = wrelh; cj.n4[4] = 512 * 512 / 4;
    cj.src[5] = W_q;     cj.dst[5] = wqh;   cj.n4[5] = 512 * 512 / 4;
    cj.src[6] = W_o;     cj.dst[6] = woh;   cj.n4[6] = 512 * 512 / 4;
    int total4 = (6144 * 512 + 2048 * 512 + 8192 * 512 +
                  512 * 1024 + 3 * 512 * 512) / 4;
    conv_f2h<<<(total4 + 255) / 256, 256>>>(cj, total4);

    // 1) all 4 projections (fp16 MMA), one launch
    DescH d0 = { memh, wkvh,  (void*)kvh,                         1024, 512, 8, 0,   1 };
    DescH d1 = { xh,   wkvh,  (void*)(kvh + (size_t)6144 * 1024), 1024, 512, 8, 384, 1 };
    DescH d2 = { posh, wrelh, (void*)relh,                        512,  512, 4, 512, 1 };
    DescH d3 = { xh,   wqh,   (void*)qh,                          512,  512, 4, 768, 1 };
    proj_h<<<832, 256, SMEM_PH>>>(d0, d1, d2, d3);

    // 2) fused scores + exp + PV
    score_pv<<<dim3(8, 32), 512, SMEM_SPV>>>(qh, pbu, pbv, kvh, relh, ib,
                                             prob, rs, vec);

    // fork: attn on s2, concurrent with gemm64+ln on the main stream
    cudaEventRecord(ev1, 0);
    cudaStreamWaitEvent(s2, ev1, 0);
    attn_kernel<<<512, 256, 0, s2>>>(prob, rs, attn);
    cudaEventRecord(ev2, s2);

    // 4) y = x + vec @ W_o ; layernorm (main stream)
    gemm64_h<<<dim3(8, 16), 256, SMEM_GH>>>(vec, woh, x, y, 2048, 512, 512);
    ln_kernel<<<2048, 256>>>(y, ln_g, ln_b, out);

    // join
    cudaStreamWaitEvent(0, ev2, 0);
}

// round 16
// speedup vs baseline: 1.0465x; 1.0465x over previous
#include <cuda_runtime.h>
#include <cuda_fp16.h>
#include <stdint.h>

// Problem constants
#define Lq     512
#define BATCH  4
#define SCALEF 0.125f
#define LOG2E  1.4426950408889634f

// ---------------- scratch ----------------
__device__ __half g_memh[(size_t)6144 * 512];
__device__ __half g_xh  [(size_t)2048 * 512];
__device__ __half g_posh[(size_t)8192 * 512];
__device__ __half g_wkvh[(size_t)512 * 1024];
__device__ __half g_wrelh[(size_t)512 * 512];
__device__ __half g_wqh [(size_t)512 * 512];
__device__ __half g_woh [(size_t)512 * 512];
__device__ __half g_kv  [(size_t)8192 * 1024];
__device__ __half g_rel [(size_t)8192 * 512];
__device__ __half g_qh  [(size_t)2048 * 512];
__device__ __half g_prob[(size_t)32 * 512 * 2048];      // i-major: [i][bn][j]
__device__ float  g_rsum[(size_t)32 * 512];
__device__ __half g_vec [(size_t)2048 * 512];
__device__ float  g_y   [(size_t)2048 * 512];

// ---------------- helpers ----------------
__device__ __forceinline__ void mma_f16(float* d, const uint32_t* a,
                                        const uint32_t* b, const float* c) {
    asm volatile(
        "mma.sync.aligned.m16n8k16.row.col.f32.f16.f16.f32 "
        "{%0,%1,%2,%3}, {%4,%5,%6,%7}, {%8,%9}, {%10,%11,%12,%13};"
        : "=f"(d[0]), "=f"(d[1]), "=f"(d[2]), "=f"(d[3])
        : "r"(a[0]), "r"(a[1]), "r"(a[2]), "r"(a[3]),
          "r"(b[0]), "r"(b[1]),
          "f"(c[0]), "f"(c[1]), "f"(c[2]), "f"(c[3]));
}

__device__ __forceinline__ void ldsm_x4_t(uint32_t& r0, uint32_t& r1,
                                          uint32_t& r2, uint32_t& r3, uint32_t addr) {
    asm volatile("ldmatrix.sync.aligned.m8n8.x4.trans.shared.b16 {%0,%1,%2,%3}, [%4];"
                 : "=r"(r0), "=r"(r1), "=r"(r2), "=r"(r3) : "r"(addr));
}
__device__ __forceinline__ void ldsm_x4(uint32_t& r0, uint32_t& r1,
                                        uint32_t& r2, uint32_t& r3, uint32_t addr) {
    asm volatile("ldmatrix.sync.aligned.m8n8.x4.shared.b16 {%0,%1,%2,%3}, [%4];"
                 : "=r"(r0), "=r"(r1), "=r"(r2), "=r"(r3) : "r"(addr));
}

__device__ __forceinline__ void cp16(void* dst, const void* src) {
    uint32_t d = (uint32_t)__cvta_generic_to_shared(dst);
    asm volatile("cp.async.cg.shared.global [%0], [%1], 16;" :: "r"(d), "l"(src));
}
#define CP_COMMIT() asm volatile("cp.async.commit_group;")
#define CP_WAIT1()  asm volatile("cp.async.wait_group 1;")
#define CP_WAIT2()  asm volatile("cp.async.wait_group 2;")

__device__ __forceinline__ float ex2f(float x) {
    float r;
    asm("ex2.approx.f32 %0, %1;" : "=f"(r) : "f"(x));
    return r;
}

__device__ __forceinline__ float warpRedSum(float v) {
#pragma unroll
    for (int o = 16; o > 0; o >>= 1) v += __shfl_xor_sync(0xffffffffu, v, o);
    return v;
}
__device__ __forceinline__ float blockRedSum(float v, float* red) {
    v = warpRedSum(v);
    int w = threadIdx.x >> 5, l = threadIdx.x & 31;
    if (!l) red[w] = v;
    __syncthreads();
    if (threadIdx.x < 32) {
        float x = (l < 8) ? red[l] : 0.f;
        x = warpRedSum(x);
        if (!l) red[0] = x;
    }
    __syncthreads();
    float r = red[0];
    __syncthreads();
    return r;
}

// ============================================================================
// Fused float->half conversion (7 arrays)
// ============================================================================
struct ConvJob {
    const float* src[7];
    __half* dst[7];
    int n4[7];
};

__global__ void conv_f2h(ConvJob j, int total4) {
    int idx = blockIdx.x * blockDim.x + threadIdx.x;
    if (idx >= total4) return;
    int off = idx, seg = 0;
#pragma unroll
    for (int s = 0; s < 6; s++)
        if (off >= j.n4[seg]) { off -= j.n4[seg]; seg++; }
    float4 v = ((const float4*)j.src[seg])[off];
    __half2* d = (__half2*)j.dst[seg] + off * 2;
    d[0] = __floats2half2_rn(v.x, v.y);
    d[1] = __floats2half2_rn(v.z, v.w);
}

// ============================================================================
// fp16 projection kernel (4 GEMMs, one launch). 3-stage cp.async, ldsm A+B.
// ============================================================================
struct DescH {
    const __half* A; const __half* B; void* C;
    int N, K, nblk, blk0, h;
};

#define PA_ST 40
#define PB_ST 136
__global__ __launch_bounds__(256) void proj_h(DescH d0, DescH d1, DescH d2, DescH d3) {
    extern __shared__ char smraw[];
    __half* As = (__half*)smraw;
    __half* Bs = As + 3 * 128 * PA_ST;

    DescH d = d3;
    int bid = blockIdx.x;
    if (bid < d1.blk0) d = d0;
    else if (bid < d2.blk0) d = d1;
    else if (bid < d3.blk0) d = d2;
    int local = bid - d.blk0;
    int m0 = (local / d.nblk) * 128, n0 = (local % d.nblk) * 128;
    const int N = d.N, K = d.K;

    int tid = threadIdx.x;
    int warp = tid >> 5, lane = tid & 31;
    int g = lane >> 2, c = lane & 3;
    int wm = (warp >> 2) * 64;
    int wn = (warp & 3) * 32;
    int mat = lane >> 3;
    int lrow = (mat & 1) * 8 + (lane & 7);
    int lcol = (mat >> 1) * 8;
    uint32_t a_lane_term =
        (uint32_t)((((mat & 1) * 8 + (lane & 7)) * PA_ST + (mat >> 1) * 8) * 2);

    float acc[4][4][4];
#pragma unroll
    for (int mt = 0; mt < 4; mt++)
#pragma unroll
        for (int nt = 0; nt < 4; nt++)
#pragma unroll
            for (int e = 0; e < 4; e++) acc[mt][nt][e] = 0.f;

    int nk = K >> 5;
    auto loadStage = [&](int st, int k0) {
#pragma unroll
        for (int w = 0; w < 2; w++) {
            int idx = tid + w * 256;
            int r = idx >> 2, ch = (idx & 3) * 8;
            cp16(As + st * 128 * PA_ST + r * PA_ST + ch,
                 d.A + (size_t)(m0 + r) * K + k0 + ch);
        }
#pragma unroll
        for (int w = 0; w < 2; w++) {
            int idx = tid + w * 256;
            int r = idx >> 4, ch = (idx & 15) * 8;
            cp16(Bs + st * 32 * PB_ST + r * PB_ST + ch,
                 d.B + (size_t)(k0 + r) * N + n0 + ch);
        }
    };

    loadStage(0, 0);
    CP_COMMIT();
    loadStage(1, 32);
    CP_COMMIT();

    int st = 0;
    for (int kt = 0; kt < nk; kt++) {
        if (kt + 2 < nk) loadStage((st + 2) % 3, (kt + 2) * 32);
        CP_COMMIT();
        CP_WAIT2();
        __syncthreads();

        uint32_t abase = (uint32_t)__cvta_generic_to_shared(As + st * 128 * PA_ST)
                         + a_lane_term;
        uint32_t bbase = (uint32_t)__cvta_generic_to_shared(Bs + st * 32 * PB_ST);
#pragma unroll
        for (int ks = 0; ks < 2; ks++) {
            int k = ks * 16;
            uint32_t af[4][4], bf[4][2];
#pragma unroll
            for (int mt = 0; mt < 4; mt++) {
                uint32_t addr = abase +
                    (uint32_t)(((wm + mt * 16) * PA_ST + k) * 2);
                ldsm_x4(af[mt][0], af[mt][1], af[mt][2], af[mt][3], addr);
            }
#pragma unroll
            for (int p = 0; p < 2; p++) {
                uint32_t addr = bbase +
                    (uint32_t)(((k + lrow) * PB_ST + wn + p * 16 + lcol) * 2);
                uint32_t r0, r1, r2, r3;
                ldsm_x4_t(r0, r1, r2, r3, addr);
                bf[2 * p][0] = r0; bf[2 * p][1] = r1;
                bf[2 * p + 1][0] = r2; bf[2 * p + 1][1] = r3;
            }
#pragma unroll
            for (int mt = 0; mt < 4; mt++)
#pragma unroll
                for (int nt = 0; nt < 4; nt++)
                    mma_f16(acc[mt][nt], af[mt], bf[nt], acc[mt][nt]);
        }
        __syncthreads();
        st = (st + 1) % 3;
    }

#pragma unroll
    for (int mt = 0; mt < 4; mt++)
#pragma unroll
        for (int nt = 0; nt < 4; nt++) {
            int row = m0 + wm + mt * 16 + g;
            int col = n0 + wn + nt * 8 + c * 2;
            if (d.h) {
                __half* Ch = (__half*)d.C;
                *(__half2*)(Ch + (size_t)row * N + col) =
                    __floats2half2_rn(acc[mt][nt][0], acc[mt][nt][1]);
                *(__half2*)(Ch + (size_t)(row + 8) * N + col) =
                    __floats2half2_rn(acc[mt][nt][2], acc[mt][nt][3]);
            } else {
                float* Cf = (float*)d.C;
                *(float2*)(Cf + (size_t)row * N + col) =
                    make_float2(acc[mt][nt][0], acc[mt][nt][1]);
                *(float2*)(Cf + (size_t)(row + 8) * N + col) =
                    make_float2(acc[mt][nt][2], acc[mt][nt][3]);
            }
        }
}

// ============================================================================
// fp16 GEMM BN=64 with fp32 residual add (W_o)
// ============================================================================
#define GB_ST 72
__global__ __launch_bounds__(256) void gemm64_h(
        const __half* __restrict__ A, const __half* __restrict__ B,
        const float* __restrict__ Cadd, float* __restrict__ C,
        int M, int N, int K) {
    extern __shared__ char smraw[];
    __half* As = (__half*)smraw;
    __half* Bs = As + 2 * 128 * PA_ST;

    int m0 = blockIdx.y * 128, n0 = blockIdx.x * 64;
    int tid = threadIdx.x;
    int warp = tid >> 5, lane = tid & 31;
    int g = lane >> 2, c = lane & 3;
    int wm = (warp >> 2) * 64;
    int wn = (warp & 3) * 16;
    int mat = lane >> 3;
    int lrow = (mat & 1) * 8 + (lane & 7);
    int lcol = (mat >> 1) * 8;
    uint32_t a_lane_term =
        (uint32_t)((((mat & 1) * 8 + (lane & 7)) * PA_ST + (mat >> 1) * 8) * 2);

    float acc[4][2][4];
#pragma unroll
    for (int mt = 0; mt < 4; mt++)
#pragma unroll
        for (int nt = 0; nt < 2; nt++)
#pragma unroll
            for (int e = 0; e < 4; e++) acc[mt][nt][e] = 0.f;

    int nk = K >> 5;
    auto loadStage = [&](int st, int k0) {
#pragma unroll
        for (int w = 0; w < 2; w++) {
            int idx = tid + w * 256;
            int r = idx >> 2, ch = (idx & 3) * 8;
            cp16(As + st * 128 * PA_ST + r * PA_ST + ch,
                 A + (size_t)(m0 + r) * K + k0 + ch);
        }
        {
            int r = tid >> 3, ch = (tid & 7) * 8;
            if (r < 32)
                cp16(Bs + st * 32 * GB_ST + r * GB_ST + ch,
                     B + (size_t)(k0 + r) * N + n0 + ch);
        }
    };

    loadStage(0, 0);
    CP_COMMIT();

    for (int kt = 0; kt < nk; kt++) {
        int cur = kt & 1;
        if (kt + 1 < nk) loadStage((kt + 1) & 1, (kt + 1) * 32);
        CP_COMMIT();
        CP_WAIT1();
        __syncthreads();

        uint32_t abase = (uint32_t)__cvta_generic_to_shared(As + cur * 128 * PA_ST)
                         + a_lane_term;
        uint32_t bbase = (uint32_t)__cvta_generic_to_shared(Bs + cur * 32 * GB_ST);
#pragma unroll
        for (int ks = 0; ks < 2; ks++) {
            int k = ks * 16;
            uint32_t af[4][4], bf[2][2];
#pragma unroll
            for (int mt = 0; mt < 4; mt++) {
                uint32_t addr = abase +
                    (uint32_t)(((wm + mt * 16) * PA_ST + k) * 2);
                ldsm_x4(af[mt][0], af[mt][1], af[mt][2], af[mt][3], addr);
            }
            {
                uint32_t addr = bbase +
                    (uint32_t)(((k + lrow) * GB_ST + wn + lcol) * 2);
                uint32_t r0, r1, r2, r3;
                ldsm_x4_t(r0, r1, r2, r3, addr);
                bf[0][0] = r0; bf[0][1] = r1;
                bf[1][0] = r2; bf[1][1] = r3;
            }
#pragma unroll
            for (int mt = 0; mt < 4; mt++)
#pragma unroll
                for (int nt = 0; nt < 2; nt++)
                    mma_f16(acc[mt][nt], af[mt], bf[nt], acc[mt][nt]);
        }
        __syncthreads();
    }

#pragma unroll
    for (int mt = 0; mt < 4; mt++)
#pragma unroll
        for (int nt = 0; nt < 2; nt++) {
            int row = m0 + wm + mt * 16 + g;
            int col = n0 + wn + nt * 8 + c * 2;
            const float* a0 = Cadd + (size_t)row * N + col;
            const float* a1 = Cadd + (size_t)(row + 8) * N + col;
            *(float2*)(C + (size_t)row * N + col) =
                make_float2(acc[mt][nt][0] + a0[0], acc[mt][nt][1] + a0[1]);
            *(float2*)(C + (size_t)(row + 8) * N + col) =
                make_float2(acc[mt][nt][2] + a1[0], acc[mt][nt][3] + a1[1]);
        }
}

// ============================================================================
// FLASH-FUSED score + exp + PV kernel, 512 threads (16 warps: 4 m x 4 j).
// No P zero-fill for skipped tiles (attn masks analytically).
// ============================================================================
__global__ __launch_bounds__(512, 1) void score_pv(
        const __half* __restrict__ Q, const float* __restrict__ pbu,
        const float* __restrict__ pbv, const __half* __restrict__ KV,
        const __half* __restrict__ REL, const float* __restrict__ ib,
        __half* __restrict__ P, float* __restrict__ rsum,
        __half* __restrict__ vec) {
    extern __shared__ char smraw[];
    __half* qu_s  = (__half*)smraw;               // [64][72]
    __half* qv_s  = qu_s + 64 * 72;               // [64][72]
    __half* k_s   = qv_s + 64 * 72;               // [2][128*72]
    __half* v_s   = k_s + 2 * 128 * 72;           // [2][128*72]
    __half* rel_s = v_s + 2 * 128 * 72;           // [2][128*72]
    float*  bd_s  = (float*)(rel_s + 2 * 128 * 72);  // [2][64*132]; vb aliases
    float*  rows  = bd_s + 2 * 64 * 132;          // [64]
    float*  gate_s = rows + 64;                   // [64][4]

    int bn = blockIdx.y;
    int b = bn >> 3, n = bn & 7;
    int i0 = blockIdx.x * 64;
    int tid = threadIdx.x;
    int m_base = 448 - i0;

    if (tid < 64) rows[tid] = 0.f;
    if (tid < 256)
        gate_s[tid] = ib[((size_t)(i0 + (tid >> 2)) * 4 + b) * 4 + (tid & 3)];

    const float QS = SCALEF * LOG2E;
#pragma unroll
    for (int w = 0; w < 2; w++) {
        int idx = tid + w * 512;
        int r = idx >> 4, c4 = (idx & 15) * 4;
        const __half2* qsrc =
            (const __half2*)(Q + (size_t)(i0 + r) * 2048 + b * 512 + n * 64 + c4);
        float2 q0 = __half22float2(qsrc[0]);
        float2 q1 = __half22float2(qsrc[1]);
        float4 bu = *(const float4*)(pbu + n * 64 + c4);
        float4 bv = *(const float4*)(pbv + n * 64 + c4);
        *(__half2*)(qu_s + r * 72 + c4) =
            __floats2half2_rn((q0.x + bu.x) * QS, (q0.y + bu.y) * QS);
        *(__half2*)(qu_s + r * 72 + c4 + 2) =
            __floats2half2_rn((q1.x + bu.z) * QS, (q1.y + bu.w) * QS);
        *(__half2*)(qv_s + r * 72 + c4) =
            __floats2half2_rn((q0.x + bv.x) * QS, (q0.y + bv.y) * QS);
        *(__half2*)(qv_s + r * 72 + c4 + 2) =
            __floats2half2_rn((q1.x + bv.z) * QS, (q1.y + bv.w) * QS);
    }

    const __half* Kb = KV + b * 1024 + n * 64;
    const __half* Vb = KV + b * 1024 + 512 + n * 64;
    const __half* Rb = REL + b * 512 + n * 64;

    auto loadK = [&](int st, int j0) {
#pragma unroll
        for (int w = 0; w < 2; w++) {
            int idx = tid + w * 512;
            int r = idx >> 3, ch = (idx & 7) * 8;
            cp16(k_s + st * 128 * 72 + r * 72 + ch,
                 Kb + (size_t)(j0 + r) * 4096 + ch);
        }
    };
    auto loadV = [&](int st, int j0) {
#pragma unroll
        for (int w = 0; w < 2; w++) {
            int idx = tid + w * 512;
            int r = idx >> 3, ch = (idx & 7) * 8;
            cp16(v_s + st * 128 * 72 + r * 72 + ch,
                 Vb + (size_t)(j0 + r) * 4096 + ch);
        }
    };
    auto loadR = [&](int chunk) {
        int st = chunk & 1;
        int mc = m_base + chunk * 128;
#pragma unroll
        for (int w = 0; w < 2; w++) {
            int idx = tid + w * 512;
            int r = idx >> 3, ch = (idx & 7) * 8;
            int mr = mc + r; if (mr > 2047) mr = 2047;
            cp16(rel_s + st * 128 * 72 + r * 72 + ch,
                 Rb + (size_t)mr * 2048 + ch);
        }
    };

    int ntiles = ((1599 + i0) >> 7) + 1;
    if (ntiles > 16) ntiles = 16;

    int warp = tid >> 5, lane = tid & 31;
    int g = lane >> 2, c = lane & 3;
    int wm  = (warp >> 2) * 16;
    int wj  = warp & 3;
    int wnA = wj * 32;

    int mat = lane >> 3;
    int lrow = (mat & 1) * 8 + (lane & 7);
    int lcol = (mat >> 1) * 8;
    int ntq = mat >> 1;
    int dq  = mat & 1;
    int l8  = lane & 7;
    uint32_t frag_row_term =
        (uint32_t)(((wnA + ntq * 8 + l8) * 72 + dq * 8) * 2);

    // prologue loads
    loadR(0);
    CP_COMMIT();
    loadK(0, 0); loadV(0, 0); loadR(1);
    CP_COMMIT();
    CP_WAIT1();
    __syncthreads();

    // hoist q fragments
    uint32_t au_r[4][4], av_r[4][4];
#pragma unroll
    for (int kk = 0; kk < 4; kk++) {
        int k = kk * 16;
        const __half* bu = qu_s + (wm + g) * 72 + k + 2 * c;
        const __half* bv = qv_s + (wm + g) * 72 + k + 2 * c;
        au_r[kk][0] = *(const uint32_t*)(bu);
        au_r[kk][1] = *(const uint32_t*)(bu + 8 * 72);
        au_r[kk][2] = *(const uint32_t*)(bu + 8);
        au_r[kk][3] = *(const uint32_t*)(bu + 8 * 72 + 8);
        av_r[kk][0] = *(const uint32_t*)(bv);
        av_r[kk][1] = *(const uint32_t*)(bv + 8 * 72);
        av_r[kk][2] = *(const uint32_t*)(bv + 8);
        av_r[kk][3] = *(const uint32_t*)(bv + 8 * 72 + 8);
    }

    // BD chunk 0 -> bd_s[0]
    {
        uint32_t rbase = (uint32_t)__cvta_generic_to_shared(rel_s) + frag_row_term;
        float accb[4][4];
#pragma unroll
        for (int nt = 0; nt < 4; nt++)
#pragma unroll
            for (int e = 0; e < 4; e++) accb[nt][e] = 0.f;
#pragma unroll
        for (int kk = 0; kk < 4; kk++) {
            uint32_t br[4][2];
            ldsm_x4(br[0][0], br[0][1], br[1][0], br[1][1], rbase + kk * 32);
            ldsm_x4(br[2][0], br[2][1], br[3][0], br[3][1], rbase + 2304 + kk * 32);
#pragma unroll
            for (int nt = 0; nt < 4; nt++)
                mma_f16(accb[nt], av_r[kk], br[nt], accb[nt]);
        }
#pragma unroll
        for (int nt = 0; nt < 4; nt++) {
            int row = wm + g;
            int col = wnA + nt * 8 + c * 2;
            *(float2*)(bd_s + row * 132 + col) = make_float2(accb[nt][0], accb[nt][1]);
            *(float2*)(bd_s + (row + 8) * 132 + col) = make_float2(accb[nt][2], accb[nt][3]);
        }
    }

    float rs[2] = {0.f, 0.f};
    float pvacc[8][4];
#pragma unroll
    for (int nd = 0; nd < 8; nd++)
#pragma unroll
        for (int e = 0; e < 4; e++) pvacc[nd][e] = 0.f;

    __half* Pb = P + ((size_t)i0 * 32 + bn) * 2048;

    for (int jt = 0; jt < ntiles; jt++) {
        int cur = jt & 1;
        if (jt + 1 < ntiles) {
            loadK((jt + 1) & 1, (jt + 1) * 128);
            loadV((jt + 1) & 1, (jt + 1) * 128);
        }
        if (jt + 2 <= ntiles) loadR(jt + 2);
        CP_COMMIT();
        CP_WAIT1();
        __syncthreads();

        uint32_t kfb = (uint32_t)__cvta_generic_to_shared(k_s + cur * 128 * 72) + frag_row_term;
        uint32_t rfb = (uint32_t)__cvta_generic_to_shared(rel_s + ((jt + 1) & 1) * 128 * 72) + frag_row_term;

        float acca[4][4], accb[4][4];
#pragma unroll
        for (int nt = 0; nt < 4; nt++)
#pragma unroll
            for (int e = 0; e < 4; e++) { acca[nt][e] = 0.f; accb[nt][e] = 0.f; }

#pragma unroll
        for (int kk = 0; kk < 4; kk++) {
            uint32_t bk[4][2], br[4][2];
            ldsm_x4(bk[0][0], bk[0][1], bk[1][0], bk[1][1], kfb + kk * 32);
            ldsm_x4(bk[2][0], bk[2][1], bk[3][0], bk[3][1], kfb + 2304 + kk * 32);
            ldsm_x4(br[0][0], br[0][1], br[1][0], br[1][1], rfb + kk * 32);
            ldsm_x4(br[2][0], br[2][1], br[3][0], br[3][1], rfb + 2304 + kk * 32);
#pragma unroll
            for (int nt = 0; nt < 4; nt++) {
                mma_f16(acca[nt], au_r[kk], bk[nt], acca[nt]);
                mma_f16(accb[nt], av_r[kk], br[nt], accb[nt]);
            }
        }

        // store BD chunk jt+1
        float* bdo = bd_s + ((jt + 1) & 1) * 64 * 132;
#pragma unroll
        for (int nt = 0; nt < 4; nt++) {
            int row = wm + g;
            int col = wnA + nt * 8 + c * 2;
            *(float2*)(bdo + row * 132 + col) = make_float2(accb[nt][0], accb[nt][1]);
            *(float2*)(bdo + (row + 8) * 132 + col) = make_float2(accb[nt][2], accb[nt][3]);
        }
        __syncthreads();

        // epilogue
        int j0 = jt * 128;
        int segA = j0 >> 9;
        bool last = (jt == ntiles - 1);
        const float* bd_lo = bd_s + (jt & 1) * 64 * 132;
        const float* bd_hi = bd_s + ((jt + 1) & 1) * 64 * 132;
        uint32_t pe2[4][2];
#pragma unroll
        for (int half = 0; half < 2; half++) {
            int i_loc = wm + g + half * 8;
            int i = i0 + i_loc;
            int mrow = j0 + 511 - i;
            float gA = gate_s[i_loc * 4 + segA];
            const float* gt = gate_s + i_loc * 4;
            int mlo = mrow + wnA;
            int slo = mlo >> 9; if (slo > 3) slo = 3;
            int shi = (mlo + 31) >> 9; if (shi > 3) shi = 3;
            float glo = gt[slo], ghi = gt[shi];
            int jcross = (((mlo >> 9) + 1) << 9) - mrow;
            int ocross = 65 + i_loc;
            const float* bdrow_lo = bd_lo + i_loc * 132 + 63 - i_loc;
            const float* bdrow_hi = bd_hi + i_loc * 132 + 63 - i_loc - 128;
            int jmax_loc = 1536 + i - j0;
#pragma unroll
            for (int nt = 0; nt < 4; nt++) {
                float a0 = acca[nt][half * 2];
                float a1 = acca[nt][half * 2 + 1];
                float pe[2];
#pragma unroll
                for (int e = 0; e < 2; e++) {
                    int j_loc = wnA + nt * 8 + c * 2 + e;
                    float gB = (j_loc >= jcross) ? ghi : glo;
                    const float* bp = (j_loc < ocross) ? bdrow_lo : bdrow_hi;
                    float bd = bp[j_loc];
                    float ac = e ? a1 : a0;
                    float s = fmaf(gA, ac, gB * bd);
                    pe[e] = ex2f(s);
                }
                if (last) {
                    int j_loc0 = wnA + nt * 8 + c * 2;
                    if (j_loc0 > jmax_loc) pe[0] = 0.f;
                    if (j_loc0 + 1 > jmax_loc) pe[1] = 0.f;
                }
                rs[half] += pe[0] + pe[1];
                __half2 h2 = __floats2half2_rn(pe[0], pe[1]);
                pe2[nt][half] = *(uint32_t*)&h2;
                *(__half2*)(Pb + (size_t)i_loc * 65536 + j0 + wnA + nt * 8 + c * 2) = h2;
            }
        }

        // PV MMA
        {
            uint32_t vbase = (uint32_t)__cvta_generic_to_shared(v_s + cur * 128 * 72);
#pragma unroll
            for (int kk2 = 0; kk2 < 2; kk2++) {
                uint32_t bf[8][2];
#pragma unroll
                for (int p = 0; p < 4; p++) {
                    uint32_t addr = vbase +
                        (uint32_t)(((wnA + kk2 * 16 + lrow) * 72 + p * 16 + lcol) * 2);
                    uint32_t r0, r1, r2, r3;
                    ldsm_x4_t(r0, r1, r2, r3, addr);
                    bf[2 * p][0] = r0; bf[2 * p][1] = r1;
                    bf[2 * p + 1][0] = r2; bf[2 * p + 1][1] = r3;
                }
                uint32_t af[4];
                af[0] = pe2[2 * kk2][0];
                af[1] = pe2[2 * kk2][1];
                af[2] = pe2[2 * kk2 + 1][0];
                af[3] = pe2[2 * kk2 + 1][1];
#pragma unroll
                for (int nd = 0; nd < 8; nd++)
                    mma_f16(pvacc[nd], af, bf[nd], pvacc[nd]);
            }
        }
        __syncthreads();
    }

    atomicAdd(&rows[wm + g], rs[0]);
    atomicAdd(&rows[wm + g + 8], rs[1]);
    __syncthreads();
    if (tid < 64) rows[tid] = 1.f / rows[tid];

    float* vb = bd_s;
    for (int idx = tid; idx < 64 * 68; idx += 512) vb[idx] = 0.f;
    __syncthreads();

    for (int r = 0; r < 4; r++) {
        if (wj == r) {
#pragma unroll
            for (int nd = 0; nd < 8; nd++)
#pragma unroll
                for (int e = 0; e < 4; e++) {
                    int row = wm + g + ((e >> 1) ? 8 : 0);
                    int col = nd * 8 + c * 2 + (e & 1);
                    vb[row * 68 + col] += pvacc[nd][e];
                }
        }
        __syncthreads();
    }

#pragma unroll
    for (int t = 0; t < 4; t++) {
        int e = tid + t * 512;
        int row = e >> 5, cp = e & 31;
        float inv = rows[row];
        float v0 = vb[row * 68 + cp * 2] * inv;
        float v1 = vb[row * 68 + cp * 2 + 1] * inv;
        *(__half2*)(vec + ((size_t)(i0 + row) * 4 + b) * 512 + n * 64 + cp * 2) =
            __floats2half2_rn(v0, v1);
    }
    if (tid < 64)
        rsum[(size_t)bn * 512 + i0 + tid] = rows[tid];
}

// ---------------- attn matrix: analytic masking ----------------------------
__global__ void attn_kernel(const __half* __restrict__ P,
                            const float* __restrict__ rsum,
                            float* __restrict__ attn) {
    __shared__ float invs[32];
    int i = blockIdx.x;
    int tid = threadIdx.x;
    if (tid < 32) invs[tid] = rsum[(size_t)tid * 512 + i];
    __syncthreads();

    int j0t = tid * 8;
    int jmax = 1536 + i;
    float* dst = attn + (size_t)i * 2048 + j0t;
    if (j0t > jmax) {
#pragma unroll
        for (int e = 0; e < 8; e++) dst[e] = 0.f;
        return;
    }

    float acc[8] = {0.f, 0.f, 0.f, 0.f, 0.f, 0.f, 0.f, 0.f};
    const __half* base = P + (size_t)i * 65536 + j0t;
#pragma unroll
    for (int bn = 0; bn < 32; bn += 8) {
        uint4 raw[8];
#pragma unroll
        for (int u = 0; u < 8; u++)
            raw[u] = *(const uint4*)(base + (size_t)(bn + u) * 2048);
#pragma unroll
        for (int u = 0; u < 8; u++) {
            float inv = invs[bn + u];
            const __half2* h = (const __half2*)&raw[u];
#pragma unroll
            for (int e = 0; e < 4; e++) {
                float2 f = __half22float2(h[e]);
                acc[e * 2]     += inv * f.x;
                acc[e * 2 + 1] += inv * f.y;
            }
        }
    }
    int nvalid = jmax - j0t + 1;
    if (nvalid > 8) nvalid = 8;
#pragma unroll
    for (int e = 0; e < 8; e++)
        dst[e] = (e < nvalid) ? acc[e] * (1.f / 32.f) : 0.f;
}

// ---------------- layernorm ----------------
__global__ void ln_kernel(const float* __restrict__ y, const float* __restrict__ g,
                          const float* __restrict__ be, float* __restrict__ out) {
    __shared__ float red[32];
    int r = blockIdx.x;
    int tid = threadIdx.x;
    float v0 = y[(size_t)r * 512 + tid];
    float v1 = y[(size_t)r * 512 + tid + 256];
    float mean = blockRedSum(v0 + v1, red) * (1.f / 512.f);
    float d0 = v0 - mean, d1 = v1 - mean;
    float var = blockRedSum(d0 * d0 + d1 * d1, red) * (1.f / 512.f);
    float rstd = rsqrtf(var + 1e-5f);
    out[(size_t)r * 512 + tid]       = d0 * rstd * g[tid] + be[tid];
    out[(size_t)r * 512 + tid + 256] = d1 * rstd * g[tid + 256] + be[tid + 256];
}

// ---------------- launch ----------------
#define SMEM_PH  ((3 * 128 * PA_ST + 3 * 32 * PB_ST) * 2)
#define SMEM_GH  ((2 * 128 * PA_ST + 2 * 32 * GB_ST) * 2)
#define SMEM_SPV ((64*72*2 + 3*2*128*72) * 2 + (2*64*132 + 64 + 256) * 4)

extern "C" void kernel_launch(void* const* d_in, const int* in_sizes, int n_in,
                              void* d_out, int out_size) {
    (void)in_sizes; (void)n_in; (void)out_size;
    const float* x       = (const float*)d_in[0];
    const float* memory  = (const float*)d_in[1];
    const float* pos_emb = (const float*)d_in[2];
    const float* pbu     = (const float*)d_in[3];
    const float* pbv     = (const float*)d_in[4];
    const float* ib      = (const float*)d_in[6];
    const float* W_q     = (const float*)d_in[7];
    const float* W_kv    = (const float*)d_in[8];
    const float* W_rel   = (const float*)d_in[9];
    const float* W_o     = (const float*)d_in[10];
    const float* ln_g    = (const float*)d_in[11];
    const float* ln_b    = (const float*)d_in[12];

    float* out  = (float*)d_out;
    float* attn = out + (size_t)Lq * BATCH * 512;

    __half *memh, *xh, *posh, *wkvh, *wrelh, *wqh, *woh;
    __half *kvh, *relh, *qh, *prob, *vec;
    float *rs, *y;
    cudaGetSymbolAddress((void**)&memh,  g_memh);
    cudaGetSymbolAddress((void**)&xh,    g_xh);
    cudaGetSymbolAddress((void**)&posh,  g_posh);
    cudaGetSymbolAddress((void**)&wkvh,  g_wkvh);
    cudaGetSymbolAddress((void**)&wrelh, g_wrelh);
    cudaGetSymbolAddress((void**)&wqh,   g_wqh);
    cudaGetSymbolAddress((void**)&woh,   g_woh);
    cudaGetSymbolAddress((void**)&kvh,   g_kv);
    cudaGetSymbolAddress((void**)&relh,  g_rel);
    cudaGetSymbolAddress((void**)&qh,    g_qh);
    cudaGetSymbolAddress((void**)&prob,  g_prob);
    cudaGetSymbolAddress((void**)&rs,    g_rsum);
    cudaGetSymbolAddress((void**)&vec,   g_vec);
    cudaGetSymbolAddress((void**)&y,     g_y);

    static bool attr_set = false;
    if (!attr_set) {
        cudaFuncSetAttribute(proj_h,
                             cudaFuncAttributeMaxDynamicSharedMemorySize, SMEM_PH);
        cudaFuncSetAttribute(gemm64_h,
                             cudaFuncAttributeMaxDynamicSharedMemorySize, SMEM_GH);
        cudaFuncSetAttribute(score_pv,
                             cudaFuncAttributeMaxDynamicSharedMemorySize, SMEM_SPV);
        attr_set = true;
    }

    // 0) convert fp32 inputs -> fp16
    ConvJob cj;
    cj.src[0] = memory;  cj.dst[0] = memh;  cj.n4[0] = 6144 * 512 / 4;
    cj.src[1] = x;       cj.dst[1] = xh;    cj.n4[1] = 2048 * 512 / 4;
    cj.src[2] = pos_emb; cj.dst[2] = posh;  cj.n4[2] = 8192 * 512 / 4;
    cj.src[3] = W_kv;    cj.dst[3] = wkvh;  cj.n4[3] = 512 * 1024 / 4;
    cj.src[4] = W_rel;   cj.dst[4] = wrelh; cj.n4[4] = 512 * 512 / 4;
    cj.src[5] = W_q;     cj.dst[5] = wqh;   cj.n4[5] = 512 * 512 / 4;
    cj.src[6] = W_o;     cj.dst[6] = woh;   cj.n4[6] = 512 * 512 / 4;
    int total4 = (6144 * 512 + 2048 * 512 + 8192 * 512 +
                  512 * 1024 + 3 * 512 * 512) / 4;
    conv_f2h<<<(total4 + 255) / 256, 256>>>(cj, total4);

    // 1) all 4 projections (fp16 MMA), one launch
    DescH d0 = { memh, wkvh,  (void*)kvh,                         1024, 512, 8, 0,   1 };
    DescH d1 = { xh,   wkvh,  (void*)(kvh + (size_t)6144 * 1024), 1024, 512, 8, 384, 1 };
    DescH d2 = { posh, wrelh, (void*)relh,                        512,  512, 4, 512, 1 };
    DescH d3 = { xh,   wqh,   (void*)qh,                          512,  512, 4, 768, 1 };
    proj_h<<<832, 256, SMEM_PH>>>(d0, d1, d2, d3);

    // 2) fused scores + exp + PV
    score_pv<<<dim3(8, 32), 512, SMEM_SPV>>>(qh, pbu, pbv, kvh, relh, ib,
                                             prob, rs, vec);

    // 3) attn matrix (single stream — fork regressed in R15)
    attn_kernel<<<512, 256>>>(prob, rs, attn);

    // 4) y = x + vec @ W_o ; layernorm
    gemm64_h<<<dim3(8, 16), 256, SMEM_GH>>>(vec, woh, x, y, 2048, 512, 512);
    ln_kernel<<<2048, 256>>>(y, ln_g, ln_b, out);
}

// round 17
// speedup vs baseline: 1.0877x; 1.0394x over previous
#include <cuda_runtime.h>
#include <cuda_fp16.h>
#include <stdint.h>

// Problem constants
#define Lq     512
#define BATCH  4
#define SCALEF 0.125f
#define LOG2E  1.4426950408889634f

// ---------------- scratch ----------------
__device__ __half g_memh[(size_t)6144 * 512];
__device__ __half g_xh  [(size_t)2048 * 512];
__device__ __half g_posh[(size_t)8192 * 512];
__device__ __half g_wkvh[(size_t)512 * 1024];
__device__ __half g_wrelh[(size_t)512 * 512];
__device__ __half g_wqh [(size_t)512 * 512];
__device__ __half g_woh [(size_t)512 * 512];
__device__ __half g_kv  [(size_t)8192 * 1024];
__device__ __half g_rel [(size_t)8192 * 512];
__device__ __half g_qh  [(size_t)2048 * 512];
__device__ __half g_prob[(size_t)32 * 512 * 2048];      // i-major: [i][bn][j]
__device__ float  g_rsum[(size_t)32 * 512];
__device__ __half g_vec [(size_t)2048 * 512];
__device__ float  g_y   [(size_t)2048 * 512];

// ---------------- helpers ----------------
__device__ __forceinline__ void mma_f16(float* d, const uint32_t* a,
                                        const uint32_t* b, const float* c) {
    asm volatile(
        "mma.sync.aligned.m16n8k16.row.col.f32.f16.f16.f32 "
        "{%0,%1,%2,%3}, {%4,%5,%6,%7}, {%8,%9}, {%10,%11,%12,%13};"
        : "=f"(d[0]), "=f"(d[1]), "=f"(d[2]), "=f"(d[3])
        : "r"(a[0]), "r"(a[1]), "r"(a[2]), "r"(a[3]),
          "r"(b[0]), "r"(b[1]),
          "f"(c[0]), "f"(c[1]), "f"(c[2]), "f"(c[3]));
}

__device__ __forceinline__ void ldsm_x4_t(uint32_t& r0, uint32_t& r1,
                                          uint32_t& r2, uint32_t& r3, uint32_t addr) {
    asm volatile("ldmatrix.sync.aligned.m8n8.x4.trans.shared.b16 {%0,%1,%2,%3}, [%4];"
                 : "=r"(r0), "=r"(r1), "=r"(r2), "=r"(r3) : "r"(addr));
}
__device__ __forceinline__ void ldsm_x4(uint32_t& r0, uint32_t& r1,
                                        uint32_t& r2, uint32_t& r3, uint32_t addr) {
    asm volatile("ldmatrix.sync.aligned.m8n8.x4.shared.b16 {%0,%1,%2,%3}, [%4];"
                 : "=r"(r0), "=r"(r1), "=r"(r2), "=r"(r3) : "r"(addr));
}

__device__ __forceinline__ void cp16(void* dst, const void* src) {
    uint32_t d = (uint32_t)__cvta_generic_to_shared(dst);
    asm volatile("cp.async.cg.shared.global [%0], [%1], 16;" :: "r"(d), "l"(src));
}
#define CP_COMMIT() asm volatile("cp.async.commit_group;")
#define CP_WAIT0()  asm volatile("cp.async.wait_group 0;")
#define CP_WAIT1()  asm volatile("cp.async.wait_group 1;")
#define CP_WAIT2()  asm volatile("cp.async.wait_group 2;")

__device__ __forceinline__ float ex2f(float x) {
    float r;
    asm("ex2.approx.f32 %0, %1;" : "=f"(r) : "f"(x));
    return r;
}

__device__ __forceinline__ float warpRedSum(float v) {
#pragma unroll
    for (int o = 16; o > 0; o >>= 1) v += __shfl_xor_sync(0xffffffffu, v, o);
    return v;
}
__device__ __forceinline__ float blockRedSum(float v, float* red) {
    v = warpRedSum(v);
    int w = threadIdx.x >> 5, l = threadIdx.x & 31;
    if (!l) red[w] = v;
    __syncthreads();
    if (threadIdx.x < 32) {
        float x = (l < 8) ? red[l] : 0.f;
        x = warpRedSum(x);
        if (!l) red[0] = x;
    }
    __syncthreads();
    float r = red[0];
    __syncthreads();
    return r;
}

// ============================================================================
// Fused float->half conversion (7 arrays)
// ============================================================================
struct ConvJob {
    const float* src[7];
    __half* dst[7];
    int n4[7];
};

__global__ void conv_f2h(ConvJob j, int total4) {
    int idx = blockIdx.x * blockDim.x + threadIdx.x;
    if (idx >= total4) return;
    int off = idx, seg = 0;
#pragma unroll
    for (int s = 0; s < 6; s++)
        if (off >= j.n4[seg]) { off -= j.n4[seg]; seg++; }
    float4 v = ((const float4*)j.src[seg])[off];
    __half2* d = (__half2*)j.dst[seg] + off * 2;
    d[0] = __floats2half2_rn(v.x, v.y);
    d[1] = __floats2half2_rn(v.z, v.w);
}

// ============================================================================
// fp16 projection kernel (4 GEMMs, one launch). 3-stage cp.async, ldsm A+B.
// ============================================================================
struct DescH {
    const __half* A; const __half* B; void* C;
    int N, K, nblk, blk0, h;
};

#define PA_ST 40
#define PB_ST 136
__global__ __launch_bounds__(256) void proj_h(DescH d0, DescH d1, DescH d2, DescH d3) {
    extern __shared__ char smraw[];
    __half* As = (__half*)smraw;
    __half* Bs = As + 3 * 128 * PA_ST;

    DescH d = d3;
    int bid = blockIdx.x;
    if (bid < d1.blk0) d = d0;
    else if (bid < d2.blk0) d = d1;
    else if (bid < d3.blk0) d = d2;
    int local = bid - d.blk0;
    int m0 = (local / d.nblk) * 128, n0 = (local % d.nblk) * 128;
    const int N = d.N, K = d.K;

    int tid = threadIdx.x;
    int warp = tid >> 5, lane = tid & 31;
    int g = lane >> 2, c = lane & 3;
    int wm = (warp >> 2) * 64;
    int wn = (warp & 3) * 32;
    int mat = lane >> 3;
    int lrow = (mat & 1) * 8 + (lane & 7);
    int lcol = (mat >> 1) * 8;
    uint32_t a_lane_term =
        (uint32_t)((((mat & 1) * 8 + (lane & 7)) * PA_ST + (mat >> 1) * 8) * 2);

    float acc[4][4][4];
#pragma unroll
    for (int mt = 0; mt < 4; mt++)
#pragma unroll
        for (int nt = 0; nt < 4; nt++)
#pragma unroll
            for (int e = 0; e < 4; e++) acc[mt][nt][e] = 0.f;

    int nk = K >> 5;
    auto loadStage = [&](int st, int k0) {
#pragma unroll
        for (int w = 0; w < 2; w++) {
            int idx = tid + w * 256;
            int r = idx >> 2, ch = (idx & 3) * 8;
            cp16(As + st * 128 * PA_ST + r * PA_ST + ch,
                 d.A + (size_t)(m0 + r) * K + k0 + ch);
        }
#pragma unroll
        for (int w = 0; w < 2; w++) {
            int idx = tid + w * 256;
            int r = idx >> 4, ch = (idx & 15) * 8;
            cp16(Bs + st * 32 * PB_ST + r * PB_ST + ch,
                 d.B + (size_t)(k0 + r) * N + n0 + ch);
        }
    };

    loadStage(0, 0);
    CP_COMMIT();
    loadStage(1, 32);
    CP_COMMIT();

    int st = 0;
    for (int kt = 0; kt < nk; kt++) {
        if (kt + 2 < nk) loadStage((st + 2) % 3, (kt + 2) * 32);
        CP_COMMIT();
        CP_WAIT2();
        __syncthreads();

        uint32_t abase = (uint32_t)__cvta_generic_to_shared(As + st * 128 * PA_ST)
                         + a_lane_term;
        uint32_t bbase = (uint32_t)__cvta_generic_to_shared(Bs + st * 32 * PB_ST);
#pragma unroll
        for (int ks = 0; ks < 2; ks++) {
            int k = ks * 16;
            uint32_t af[4][4], bf[4][2];
#pragma unroll
            for (int mt = 0; mt < 4; mt++) {
                uint32_t addr = abase +
                    (uint32_t)(((wm + mt * 16) * PA_ST + k) * 2);
                ldsm_x4(af[mt][0], af[mt][1], af[mt][2], af[mt][3], addr);
            }
#pragma unroll
            for (int p = 0; p < 2; p++) {
                uint32_t addr = bbase +
                    (uint32_t)(((k + lrow) * PB_ST + wn + p * 16 + lcol) * 2);
                uint32_t r0, r1, r2, r3;
                ldsm_x4_t(r0, r1, r2, r3, addr);
                bf[2 * p][0] = r0; bf[2 * p][1] = r1;
                bf[2 * p + 1][0] = r2; bf[2 * p + 1][1] = r3;
            }
#pragma unroll
            for (int mt = 0; mt < 4; mt++)
#pragma unroll
                for (int nt = 0; nt < 4; nt++)
                    mma_f16(acc[mt][nt], af[mt], bf[nt], acc[mt][nt]);
        }
        __syncthreads();
        st = (st + 1) % 3;
    }

#pragma unroll
    for (int mt = 0; mt < 4; mt++)
#pragma unroll
        for (int nt = 0; nt < 4; nt++) {
            int row = m0 + wm + mt * 16 + g;
            int col = n0 + wn + nt * 8 + c * 2;
            if (d.h) {
                __half* Ch = (__half*)d.C;
                *(__half2*)(Ch + (size_t)row * N + col) =
                    __floats2half2_rn(acc[mt][nt][0], acc[mt][nt][1]);
                *(__half2*)(Ch + (size_t)(row + 8) * N + col) =
                    __floats2half2_rn(acc[mt][nt][2], acc[mt][nt][3]);
            } else {
                float* Cf = (float*)d.C;
                *(float2*)(Cf + (size_t)row * N + col) =
                    make_float2(acc[mt][nt][0], acc[mt][nt][1]);
                *(float2*)(Cf + (size_t)(row + 8) * N + col) =
                    make_float2(acc[mt][nt][2], acc[mt][nt][3]);
            }
        }
}

// ============================================================================
// FUSED gemm64 (W_o, fp32 residual) + attn-matrix kernel.
// Blocks 0..127: gemm (vec @ W_o + x -> y). Blocks 128..639: attn row i.
// Both depend only on score_pv outputs -> natural overlap in one launch.
// ============================================================================
#define GB_ST 72
__global__ __launch_bounds__(256) void gemm_attn(
        const __half* __restrict__ A, const __half* __restrict__ B,
        const float* __restrict__ Cadd, float* __restrict__ C,
        const __half* __restrict__ P, const float* __restrict__ rsum,
        float* __restrict__ attn) {
    extern __shared__ char smraw[];
    int tid = threadIdx.x;

    if (blockIdx.x >= 128) {
        // ---- attn branch ----
        float* invs = (float*)smraw;
        int i = blockIdx.x - 128;
        if (tid < 32) invs[tid] = rsum[(size_t)tid * 512 + i];
        __syncthreads();

        int j0t = tid * 8;
        int jmax = 1536 + i;
        float* dst = attn + (size_t)i * 2048 + j0t;
        if (j0t > jmax) {
#pragma unroll
            for (int e = 0; e < 8; e++) dst[e] = 0.f;
            return;
        }

        float acc[8] = {0.f, 0.f, 0.f, 0.f, 0.f, 0.f, 0.f, 0.f};
        const __half* base = P + (size_t)i * 65536 + j0t;
#pragma unroll
        for (int bn = 0; bn < 32; bn += 8) {
            uint4 raw[8];
#pragma unroll
            for (int u = 0; u < 8; u++)
                raw[u] = *(const uint4*)(base + (size_t)(bn + u) * 2048);
#pragma unroll
            for (int u = 0; u < 8; u++) {
                float inv = invs[bn + u];
                const __half2* h = (const __half2*)&raw[u];
#pragma unroll
                for (int e = 0; e < 4; e++) {
                    float2 f = __half22float2(h[e]);
                    acc[e * 2]     += inv * f.x;
                    acc[e * 2 + 1] += inv * f.y;
                }
            }
        }
        int nvalid = jmax - j0t + 1;
        if (nvalid > 8) nvalid = 8;
#pragma unroll
        for (int e = 0; e < 8; e++)
            dst[e] = (e < nvalid) ? acc[e] * (1.f / 32.f) : 0.f;
        return;
    }

    // ---- gemm branch ----
    const int N = 512, K = 512;
    __half* As = (__half*)smraw;
    __half* Bs = As + 2 * 128 * PA_ST;

    int gb = blockIdx.x;
    int m0 = (gb >> 3) * 128, n0 = (gb & 7) * 64;
    int warp = tid >> 5, lane = tid & 31;
    int g = lane >> 2, c = lane & 3;
    int wm = (warp >> 2) * 64;
    int wn = (warp & 3) * 16;
    int mat = lane >> 3;
    int lrow = (mat & 1) * 8 + (lane & 7);
    int lcol = (mat >> 1) * 8;
    uint32_t a_lane_term =
        (uint32_t)((((mat & 1) * 8 + (lane & 7)) * PA_ST + (mat >> 1) * 8) * 2);

    float acc[4][2][4];
#pragma unroll
    for (int mt = 0; mt < 4; mt++)
#pragma unroll
        for (int nt = 0; nt < 2; nt++)
#pragma unroll
            for (int e = 0; e < 4; e++) acc[mt][nt][e] = 0.f;

    int nk = K >> 5;
    auto loadStage = [&](int st, int k0) {
#pragma unroll
        for (int w = 0; w < 2; w++) {
            int idx = tid + w * 256;
            int r = idx >> 2, ch = (idx & 3) * 8;
            cp16(As + st * 128 * PA_ST + r * PA_ST + ch,
                 A + (size_t)(m0 + r) * K + k0 + ch);
        }
        {
            int r = tid >> 3, ch = (tid & 7) * 8;
            if (r < 32)
                cp16(Bs + st * 32 * GB_ST + r * GB_ST + ch,
                     B + (size_t)(k0 + r) * N + n0 + ch);
        }
    };

    loadStage(0, 0);
    CP_COMMIT();

    for (int kt = 0; kt < nk; kt++) {
        int cur = kt & 1;
        if (kt + 1 < nk) loadStage((kt + 1) & 1, (kt + 1) * 32);
        CP_COMMIT();
        CP_WAIT1();
        __syncthreads();

        uint32_t abase = (uint32_t)__cvta_generic_to_shared(As + cur * 128 * PA_ST)
                         + a_lane_term;
        uint32_t bbase = (uint32_t)__cvta_generic_to_shared(Bs + cur * 32 * GB_ST);
#pragma unroll
        for (int ks = 0; ks < 2; ks++) {
            int k = ks * 16;
            uint32_t af[4][4], bf[2][2];
#pragma unroll
            for (int mt = 0; mt < 4; mt++) {
                uint32_t addr = abase +
                    (uint32_t)(((wm + mt * 16) * PA_ST + k) * 2);
                ldsm_x4(af[mt][0], af[mt][1], af[mt][2], af[mt][3], addr);
            }
            {
                uint32_t addr = bbase +
                    (uint32_t)(((k + lrow) * GB_ST + wn + lcol) * 2);
                uint32_t r0, r1, r2, r3;
                ldsm_x4_t(r0, r1, r2, r3, addr);
                bf[0][0] = r0; bf[0][1] = r1;
                bf[1][0] = r2; bf[1][1] = r3;
            }
#pragma unroll
            for (int mt = 0; mt < 4; mt++)
#pragma unroll
                for (int nt = 0; nt < 2; nt++)
                    mma_f16(acc[mt][nt], af[mt], bf[nt], acc[mt][nt]);
        }
        __syncthreads();
    }

#pragma unroll
    for (int mt = 0; mt < 4; mt++)
#pragma unroll
        for (int nt = 0; nt < 2; nt++) {
            int row = m0 + wm + mt * 16 + g;
            int col = n0 + wn + nt * 8 + c * 2;
            const float* a0 = Cadd + (size_t)row * N + col;
            const float* a1 = Cadd + (size_t)(row + 8) * N + col;
            *(float2*)(C + (size_t)row * N + col) =
                make_float2(acc[mt][nt][0] + a0[0], acc[mt][nt][1] + a0[1]);
            *(float2*)(C + (size_t)(row + 8) * N + col) =
                make_float2(acc[mt][nt][2] + a1[0], acc[mt][nt][3] + a1[1]);
        }
}

// ============================================================================
// FLASH-FUSED score + exp + PV kernel, 512 threads (16 warps: 4 m x 4 j).
// 2 syncs/tile: loads issued AFTER the top barrier (wait_group 0), end-of-
// loop sync removed (next top sync provides WAR protection).
// ============================================================================
__global__ __launch_bounds__(512, 1) void score_pv(
        const __half* __restrict__ Q, const float* __restrict__ pbu,
        const float* __restrict__ pbv, const __half* __restrict__ KV,
        const __half* __restrict__ REL, const float* __restrict__ ib,
        __half* __restrict__ P, float* __restrict__ rsum,
        __half* __restrict__ vec) {
    extern __shared__ char smraw[];
    __half* qu_s  = (__half*)smraw;               // [64][72]
    __half* qv_s  = qu_s + 64 * 72;               // [64][72]
    __half* k_s   = qv_s + 64 * 72;               // [2][128*72]
    __half* v_s   = k_s + 2 * 128 * 72;           // [2][128*72]
    __half* rel_s = v_s + 2 * 128 * 72;           // [2][128*72]
    float*  bd_s  = (float*)(rel_s + 2 * 128 * 72);  // [2][64*132]; vb aliases
    float*  rows  = bd_s + 2 * 64 * 132;          // [64]
    float*  gate_s = rows + 64;                   // [64][4]

    int bn = blockIdx.y;
    int b = bn >> 3, n = bn & 7;
    int i0 = blockIdx.x * 64;
    int tid = threadIdx.x;
    int m_base = 448 - i0;

    if (tid < 64) rows[tid] = 0.f;
    if (tid < 256)
        gate_s[tid] = ib[((size_t)(i0 + (tid >> 2)) * 4 + b) * 4 + (tid & 3)];

    const float QS = SCALEF * LOG2E;
#pragma unroll
    for (int w = 0; w < 2; w++) {
        int idx = tid + w * 512;
        int r = idx >> 4, c4 = (idx & 15) * 4;
        const __half2* qsrc =
            (const __half2*)(Q + (size_t)(i0 + r) * 2048 + b * 512 + n * 64 + c4);
        float2 q0 = __half22float2(qsrc[0]);
        float2 q1 = __half22float2(qsrc[1]);
        float4 bu = *(const float4*)(pbu + n * 64 + c4);
        float4 bv = *(const float4*)(pbv + n * 64 + c4);
        *(__half2*)(qu_s + r * 72 + c4) =
            __floats2half2_rn((q0.x + bu.x) * QS, (q0.y + bu.y) * QS);
        *(__half2*)(qu_s + r * 72 + c4 + 2) =
            __floats2half2_rn((q1.x + bu.z) * QS, (q1.y + bu.w) * QS);
        *(__half2*)(qv_s + r * 72 + c4) =
            __floats2half2_rn((q0.x + bv.x) * QS, (q0.y + bv.y) * QS);
        *(__half2*)(qv_s + r * 72 + c4 + 2) =
            __floats2half2_rn((q1.x + bv.z) * QS, (q1.y + bv.w) * QS);
    }

    const __half* Kb = KV + b * 1024 + n * 64;
    const __half* Vb = KV + b * 1024 + 512 + n * 64;
    const __half* Rb = REL + b * 512 + n * 64;

    auto loadK = [&](int st, int j0) {
#pragma unroll
        for (int w = 0; w < 2; w++) {
            int idx = tid + w * 512;
            int r = idx >> 3, ch = (idx & 7) * 8;
            cp16(k_s + st * 128 * 72 + r * 72 + ch,
                 Kb + (size_t)(j0 + r) * 4096 + ch);
        }
    };
    auto loadV = [&](int st, int j0) {
#pragma unroll
        for (int w = 0; w < 2; w++) {
            int idx = tid + w * 512;
            int r = idx >> 3, ch = (idx & 7) * 8;
            cp16(v_s + st * 128 * 72 + r * 72 + ch,
                 Vb + (size_t)(j0 + r) * 4096 + ch);
        }
    };
    auto loadR = [&](int chunk) {
        int st = chunk & 1;
        int mc = m_base + chunk * 128;
#pragma unroll
        for (int w = 0; w < 2; w++) {
            int idx = tid + w * 512;
            int r = idx >> 3, ch = (idx & 7) * 8;
            int mr = mc + r; if (mr > 2047) mr = 2047;
            cp16(rel_s + st * 128 * 72 + r * 72 + ch,
                 Rb + (size_t)mr * 2048 + ch);
        }
    };

    int ntiles = ((1599 + i0) >> 7) + 1;
    if (ntiles > 16) ntiles = 16;

    int warp = tid >> 5, lane = tid & 31;
    int g = lane >> 2, c = lane & 3;
    int wm  = (warp >> 2) * 16;
    int wj  = warp & 3;
    int wnA = wj * 32;

    int mat = lane >> 3;
    int lrow = (mat & 1) * 8 + (lane & 7);
    int lcol = (mat >> 1) * 8;
    int ntq = mat >> 1;
    int dq  = mat & 1;
    int l8  = lane & 7;
    uint32_t frag_row_term =
        (uint32_t)(((wnA + ntq * 8 + l8) * 72 + dq * 8) * 2);

    // prologue loads
    loadR(0);
    CP_COMMIT();
    loadK(0, 0); loadV(0, 0); loadR(1);
    CP_COMMIT();
    CP_WAIT1();
    __syncthreads();

    // hoist q fragments
    uint32_t au_r[4][4], av_r[4][4];
#pragma unroll
    for (int kk = 0; kk < 4; kk++) {
        int k = kk * 16;
        const __half* bu = qu_s + (wm + g) * 72 + k + 2 * c;
        const __half* bv = qv_s + (wm + g) * 72 + k + 2 * c;
        au_r[kk][0] = *(const uint32_t*)(bu);
        au_r[kk][1] = *(const uint32_t*)(bu + 8 * 72);
        au_r[kk][2] = *(const uint32_t*)(bu + 8);
        au_r[kk][3] = *(const uint32_t*)(bu + 8 * 72 + 8);
        av_r[kk][0] = *(const uint32_t*)(bv);
        av_r[kk][1] = *(const uint32_t*)(bv + 8 * 72);
        av_r[kk][2] = *(const uint32_t*)(bv + 8);
        av_r[kk][3] = *(const uint32_t*)(bv + 8 * 72 + 8);
    }

    // BD chunk 0 -> bd_s[0]
    {
        uint32_t rbase = (uint32_t)__cvta_generic_to_shared(rel_s) + frag_row_term;
        float accb[4][4];
#pragma unroll
        for (int nt = 0; nt < 4; nt++)
#pragma unroll
            for (int e = 0; e < 4; e++) accb[nt][e] = 0.f;
#pragma unroll
        for (int kk = 0; kk < 4; kk++) {
            uint32_t br[4][2];
            ldsm_x4(br[0][0], br[0][1], br[1][0], br[1][1], rbase + kk * 32);
            ldsm_x4(br[2][0], br[2][1], br[3][0], br[3][1], rbase + 2304 + kk * 32);
#pragma unroll
            for (int nt = 0; nt < 4; nt++)
                mma_f16(accb[nt], av_r[kk], br[nt], accb[nt]);
        }
#pragma unroll
        for (int nt = 0; nt < 4; nt++) {
            int row = wm + g;
            int col = wnA + nt * 8 + c * 2;
            *(float2*)(bd_s + row * 132 + col) = make_float2(accb[nt][0], accb[nt][1]);
            *(float2*)(bd_s + (row + 8) * 132 + col) = make_float2(accb[nt][2], accb[nt][3]);
        }
    }

    float rs[2] = {0.f, 0.f};
    float pvacc[8][4];
#pragma unroll
    for (int nd = 0; nd < 8; nd++)
#pragma unroll
        for (int e = 0; e < 4; e++) pvacc[nd][e] = 0.f;

    __half* Pb = P + ((size_t)i0 * 32 + bn) * 2048;

    for (int jt = 0; jt < ntiles; jt++) {
        int cur = jt & 1;
        // top barrier: this tile's data complete AND all warps done with the
        // previous tile's smem reads (WAR protection for the loads below)
        CP_WAIT0();
        __syncthreads();
        if (jt + 1 < ntiles) {
            loadK((jt + 1) & 1, (jt + 1) * 128);
            loadV((jt + 1) & 1, (jt + 1) * 128);
        }
        if (jt + 2 <= ntiles) loadR(jt + 2);
        CP_COMMIT();

        uint32_t kfb = (uint32_t)__cvta_generic_to_shared(k_s + cur * 128 * 72) + frag_row_term;
        uint32_t rfb = (uint32_t)__cvta_generic_to_shared(rel_s + ((jt + 1) & 1) * 128 * 72) + frag_row_term;

        float acca[4][4], accb[4][4];
#pragma unroll
        for (int nt = 0; nt < 4; nt++)
#pragma unroll
            for (int e = 0; e < 4; e++) { acca[nt][e] = 0.f; accb[nt][e] = 0.f; }

#pragma unroll
        for (int kk = 0; kk < 4; kk++) {
            uint32_t bk[4][2], br[4][2];
            ldsm_x4(bk[0][0], bk[0][1], bk[1][0], bk[1][1], kfb + kk * 32);
            ldsm_x4(bk[2][0], bk[2][1], bk[3][0], bk[3][1], kfb + 2304 + kk * 32);
            ldsm_x4(br[0][0], br[0][1], br[1][0], br[1][1], rfb + kk * 32);
            ldsm_x4(br[2][0], br[2][1], br[3][0], br[3][1], rfb + 2304 + kk * 32);
#pragma unroll
            for (int nt = 0; nt < 4; nt++) {
                mma_f16(acca[nt], au_r[kk], bk[nt], acca[nt]);
                mma_f16(accb[nt], av_r[kk], br[nt], accb[nt]);
            }
        }

        // store BD chunk jt+1
        float* bdo = bd_s + ((jt + 1) & 1) * 64 * 132;
#pragma unroll
        for (int nt = 0; nt < 4; nt++) {
            int row = wm + g;
            int col = wnA + nt * 8 + c * 2;
            *(float2*)(bdo + row * 132 + col) = make_float2(accb[nt][0], accb[nt][1]);
            *(float2*)(bdo + (row + 8) * 132 + col) = make_float2(accb[nt][2], accb[nt][3]);
        }
        __syncthreads();

        // epilogue
        int j0 = jt * 128;
        int segA = j0 >> 9;
        bool last = (jt == ntiles - 1);
        const float* bd_lo = bd_s + (jt & 1) * 64 * 132;
        const float* bd_hi = bd_s + ((jt + 1) & 1) * 64 * 132;
        uint32_t pe2[4][2];
#pragma unroll
        for (int half = 0; half < 2; half++) {
            int i_loc = wm + g + half * 8;
            int i = i0 + i_loc;
            int mrow = j0 + 511 - i;
            float gA = gate_s[i_loc * 4 + segA];
            const float* gt = gate_s + i_loc * 4;
            int mlo = mrow + wnA;
            int slo = mlo >> 9; if (slo > 3) slo = 3;
            int shi = (mlo + 31) >> 9; if (shi > 3) shi = 3;
            float glo = gt[slo], ghi = gt[shi];
            int jcross = (((mlo >> 9) + 1) << 9) - mrow;
            int ocross = 65 + i_loc;
            const float* bdrow_lo = bd_lo + i_loc * 132 + 63 - i_loc;
            const float* bdrow_hi = bd_hi + i_loc * 132 + 63 - i_loc - 128;
            int jmax_loc = 1536 + i - j0;
#pragma unroll
            for (int nt = 0; nt < 4; nt++) {
                float a0 = acca[nt][half * 2];
                float a1 = acca[nt][half * 2 + 1];
                float pe[2];
#pragma unroll
                for (int e = 0; e < 2; e++) {
                    int j_loc = wnA + nt * 8 + c * 2 + e;
                    float gB = (j_loc >= jcross) ? ghi : glo;
                    const float* bp = (j_loc < ocross) ? bdrow_lo : bdrow_hi;
                    float bd = bp[j_loc];
                    float ac = e ? a1 : a0;
                    float s = fmaf(gA, ac, gB * bd);
                    pe[e] = ex2f(s);
                }
                if (last) {
                    int j_loc0 = wnA + nt * 8 + c * 2;
                    if (j_loc0 > jmax_loc) pe[0] = 0.f;
                    if (j_loc0 + 1 > jmax_loc) pe[1] = 0.f;
                }
                rs[half] += pe[0] + pe[1];
                __half2 h2 = __floats2half2_rn(pe[0], pe[1]);
                pe2[nt][half] = *(uint32_t*)&h2;
                *(__half2*)(Pb + (size_t)i_loc * 65536 + j0 + wnA + nt * 8 + c * 2) = h2;
            }
        }

        // PV MMA
        {
            uint32_t vbase = (uint32_t)__cvta_generic_to_shared(v_s + cur * 128 * 72);
#pragma unroll
            for (int kk2 = 0; kk2 < 2; kk2++) {
                uint32_t bf[8][2];
#pragma unroll
                for (int p = 0; p < 4; p++) {
                    uint32_t addr = vbase +
                        (uint32_t)(((wnA + kk2 * 16 + lrow) * 72 + p * 16 + lcol) * 2);
                    uint32_t r0, r1, r2, r3;
                    ldsm_x4_t(r0, r1, r2, r3, addr);
                    bf[2 * p][0] = r0; bf[2 * p][1] = r1;
                    bf[2 * p + 1][0] = r2; bf[2 * p + 1][1] = r3;
                }
                uint32_t af[4];
                af[0] = pe2[2 * kk2][0];
                af[1] = pe2[2 * kk2][1];
                af[2] = pe2[2 * kk2 + 1][0];
                af[3] = pe2[2 * kk2 + 1][1];
#pragma unroll
                for (int nd = 0; nd < 8; nd++)
                    mma_f16(pvacc[nd], af, bf[nd], pvacc[nd]);
            }
        }
        // no end-of-loop sync: next iteration's top barrier protects WAR
    }

    atomicAdd(&rows[wm + g], rs[0]);
    atomicAdd(&rows[wm + g + 8], rs[1]);
    __syncthreads();
    if (tid < 64) rows[tid] = 1.f / rows[tid];

    float* vb = bd_s;
    for (int idx = tid; idx < 64 * 68; idx += 512) vb[idx] = 0.f;
    __syncthreads();

    for (int r = 0; r < 4; r++) {
        if (wj == r) {
#pragma unroll
            for (int nd = 0; nd < 8; nd++)
#pragma unroll
                for (int e = 0; e < 4; e++) {
                    int row = wm + g + ((e >> 1) ? 8 : 0);
                    int col = nd * 8 + c * 2 + (e & 1);
                    vb[row * 68 + col] += pvacc[nd][e];
                }
        }
        __syncthreads();
    }

#pragma unroll
    for (int t = 0; t < 4; t++) {
        int e = tid + t * 512;
        int row = e >> 5, cp = e & 31;
        float inv = rows[row];
        float v0 = vb[row * 68 + cp * 2] * inv;
        float v1 = vb[row * 68 + cp * 2 + 1] * inv;
        *(__half2*)(vec + ((size_t)(i0 + row) * 4 + b) * 512 + n * 64 + cp * 2) =
            __floats2half2_rn(v0, v1);
    }
    if (tid < 64)
        rsum[(size_t)bn * 512 + i0 + tid] = rows[tid];
}

// ---------------- layernorm ----------------
__global__ void ln_kernel(const float* __restrict__ y, const float* __restrict__ g,
                          const float* __restrict__ be, float* __restrict__ out) {
    __shared__ float red[32];
    int r = blockIdx.x;
    int tid = threadIdx.x;
    float v0 = y[(size_t)r * 512 + tid];
    float v1 = y[(size_t)r * 512 + tid + 256];
    float mean = blockRedSum(v0 + v1, red) * (1.f / 512.f);
    float d0 = v0 - mean, d1 = v1 - mean;
    float var = blockRedSum(d0 * d0 + d1 * d1, red) * (1.f / 512.f);
    float rstd = rsqrtf(var + 1e-5f);
    out[(size_t)r * 512 + tid]       = d0 * rstd * g[tid] + be[tid];
    out[(size_t)r * 512 + tid + 256] = d1 * rstd * g[tid + 256] + be[tid + 256];
}

// ---------------- launch ----------------
#define SMEM_PH  ((3 * 128 * PA_ST + 3 * 32 * PB_ST) * 2)
#define SMEM_GH  ((2 * 128 * PA_ST + 2 * 32 * GB_ST) * 2)
#define SMEM_SPV ((64*72*2 + 3*2*128*72) * 2 + (2*64*132 + 64 + 256) * 4)

extern "C" void kernel_launch(void* const* d_in, const int* in_sizes, int n_in,
                              void* d_out, int out_size) {
    (void)in_sizes; (void)n_in; (void)out_size;
    const float* x       = (const float*)d_in[0];
    const float* memory  = (const float*)d_in[1];
    const float* pos_emb = (const float*)d_in[2];
    const float* pbu     = (const float*)d_in[3];
    const float* pbv     = (const float*)d_in[4];
    const float* ib      = (const float*)d_in[6];
    const float* W_q     = (const float*)d_in[7];
    const float* W_kv    = (const float*)d_in[8];
    const float* W_rel   = (const float*)d_in[9];
    const float* W_o     = (const float*)d_in[10];
    const float* ln_g    = (const float*)d_in[11];
    const float* ln_b    = (const float*)d_in[12];

    float* out  = (float*)d_out;
    float* attn = out + (size_t)Lq * BATCH * 512;

    __half *memh, *xh, *posh, *wkvh, *wrelh, *wqh, *woh;
    __half *kvh, *relh, *qh, *prob, *vec;
    float *rs, *y;
    cudaGetSymbolAddress((void**)&memh,  g_memh);
    cudaGetSymbolAddress((void**)&xh,    g_xh);
    cudaGetSymbolAddress((void**)&posh,  g_posh);
    cudaGetSymbolAddress((void**)&wkvh,  g_wkvh);
    cudaGetSymbolAddress((void**)&wrelh, g_wrelh);
    cudaGetSymbolAddress((void**)&wqh,   g_wqh);
    cudaGetSymbolAddress((void**)&woh,   g_woh);
    cudaGetSymbolAddress((void**)&kvh,   g_kv);
    cudaGetSymbolAddress((void**)&relh,  g_rel);
    cudaGetSymbolAddress((void**)&qh,    g_qh);
    cudaGetSymbolAddress((void**)&prob,  g_prob);
    cudaGetSymbolAddress((void**)&rs,    g_rsum);
    cudaGetSymbolAddress((void**)&vec,   g_vec);
    cudaGetSymbolAddress((void**)&y,     g_y);

    static bool attr_set = false;
    if (!attr_set) {
        cudaFuncSetAttribute(proj_h,
                             cudaFuncAttributeMaxDynamicSharedMemorySize, SMEM_PH);
        cudaFuncSetAttribute(gemm_attn,
                             cudaFuncAttributeMaxDynamicSharedMemorySize, SMEM_GH);
        cudaFuncSetAttribute(score_pv,
                             cudaFuncAttributeMaxDynamicSharedMemorySize, SMEM_SPV);
        attr_set = true;
    }

    // 0) convert fp32 inputs -> fp16
    ConvJob cj;
    cj.src[0] = memory;  cj.dst[0] = memh;  cj.n4[0] = 6144 * 512 / 4;
    cj.src[1] = x;       cj.dst[1] = xh;    cj.n4[1] = 2048 * 512 / 4;
    cj.src[2] = pos_emb; cj.dst[2] = posh;  cj.n4[2] = 8192 * 512 / 4;
    cj.src[3] = W_kv;    cj.dst[3] = wkvh;  cj.n4[3] = 512 * 1024 / 4;
    cj.src[4] = W_rel;   cj.dst[4] = wrelh; cj.n4[4] = 512 * 512 / 4;
    cj.src[5] = W_q;     cj.dst[5] = wqh;   cj.n4[5] = 512 * 512 / 4;
    cj.src[6] = W_o;     cj.dst[6] = woh;   cj.n4[6] = 512 * 512 / 4;
    int total4 = (6144 * 512 + 2048 * 512 + 8192 * 512 +
                  512 * 1024 + 3 * 512 * 512) / 4;
    conv_f2h<<<(total4 + 255) / 256, 256>>>(cj, total4);

    // 1) all 4 projections (fp16 MMA), one launch
    DescH d0 = { memh, wkvh,  (void*)kvh,                         1024, 512, 8, 0,   1 };
    DescH d1 = { xh,   wkvh,  (void*)(kvh + (size_t)6144 * 1024), 1024, 512, 8, 384, 1 };
    DescH d2 = { posh, wrelh, (void*)relh,                        512,  512, 4, 512, 1 };
    DescH d3 = { xh,   wqh,   (void*)qh,                          512,  512, 4, 768, 1 };
    proj_h<<<832, 256, SMEM_PH>>>(d0, d1, d2, d3);

    // 2) fused scores + exp + PV
    score_pv<<<dim3(8, 32), 512, SMEM_SPV>>>(qh, pbu, pbv, kvh, relh, ib,
                                             prob, rs, vec);

    // 3) fused gemm64 (W_o + residual) + attn matrix in ONE launch (overlap)
    gemm_attn<<<640, 256, SMEM_GH>>>(vec, woh, x, y, prob, rs, attn);

    // 4) layernorm
    ln_kernel<<<2048, 256>>>(y, ln_g, ln_b, out);
}